// round 2
// baseline (speedup 1.0000x reference)
#include <cuda_runtime.h>
#include <math.h>
#include <stdint.h>

#define UNITS   256
#define BATCH   32768
#define NLAYERS 6
#define DIN     784
#define DOUT    10

// ---------------- device-global scratch (no allocations allowed) ----------------
__device__ float g_M  [NLAYERS][UNITS * UNITS];   // B0^-1 (working)
__device__ float g_M2 [NLAYERS][UNITS * UNITS];   // Newton temp
__device__ float g_R  [NLAYERS][UNITS * UNITS];   // Newton residual
__device__ float g_MTn[NLAYERS][UNITS * UNITS];   // -(B0^-1)^T
__device__ float g_v0 [2][UNITS * BATCH];         // ping-pong activations (32MB each)
__device__ float g_v1 [2][UNITS * BATCH];

// =====================================================================
// 1) Gauss-Jordan in-place inversion (no pivoting), one CTA per matrix.
//    Matrix lives in global memory (256KB, L1/L2 resident). 1024 threads:
//    thread t handles row t>>2, 64-column chunk (t&3)*64.
// =====================================================================
__global__ __launch_bounds__(1024) void gj_invert_kernel(const float* __restrict__ B0) {
    const int l = blockIdx.x;
    float* S = g_M[l];
    const float* A = B0 + l * UNITS * UNITS;
    const int tid = threadIdx.x;

    for (int i = tid; i < UNITS * UNITS; i += 1024) S[i] = A[i];
    __syncthreads();

    __shared__ float sp[UNITS];   // scaled pivot row
    __shared__ float sf[UNITS];   // pivot column (multipliers)

    const int r  = tid >> 2;
    const int c0 = (tid & 3) * 64;

    for (int p = 0; p < UNITS; p++) {
        // snapshot pivot column before any writes this step
        if (tid < UNITS) sf[tid] = S[tid * UNITS + p];
        __syncthreads();
        const float ipiv = 1.0f / sf[p];
        if (tid < UNITS) sp[tid] = (tid == p) ? ipiv : S[p * UNITS + tid] * ipiv;
        __syncthreads();

        if (r == p) {
            // pivot row <- scaled pivot row (sp already has ipiv at col p)
            float4* dst = (float4*)&S[r * UNITS + c0];
            #pragma unroll
            for (int v = 0; v < 16; v++) {
                float4 w;
                w.x = sp[c0 + 4 * v + 0];
                w.y = sp[c0 + 4 * v + 1];
                w.z = sp[c0 + 4 * v + 2];
                w.w = sp[c0 + 4 * v + 3];
                dst[v] = w;
            }
        } else {
            const float f = sf[r];
            float4* row = (float4*)&S[r * UNITS + c0];
            #pragma unroll
            for (int v = 0; v < 16; v++) {
                float4 xv = row[v];
                xv.x -= f * sp[c0 + 4 * v + 0];
                xv.y -= f * sp[c0 + 4 * v + 1];
                xv.z -= f * sp[c0 + 4 * v + 2];
                xv.w -= f * sp[c0 + 4 * v + 3];
                row[v] = xv;
            }
            if (p >= c0 && p < c0 + 64)     // fix col p: S[r][p] = -f/piv
                S[r * UNITS + p] = -f * ipiv;
        }
        __syncthreads();
    }
}

// =====================================================================
// 2) Small 256x256x256 GEMM (Newton refinement): C = A*B  or  C = 2I - A*B
//    grid (16 row-blocks, NLAYERS), 256 threads = one output column each.
//    Buffer selectors avoid needing host-side symbol addresses.
// =====================================================================
__device__ __forceinline__ float* selbuf(int s, int l) {
    return (s == 0) ? g_M[l] : (s == 1) ? g_M2[l] : g_R[l];
}

__global__ __launch_bounds__(256) void small_gemm_kernel(const float* __restrict__ Aext,
                                                         int selA, int selB, int selC,
                                                         int mode /*1: C=2I-AB*/) {
    const int l = blockIdx.y;
    const float* A = (selA < 0) ? (Aext + l * UNITS * UNITS) : selbuf(selA, l);
    const float* Bm = selbuf(selB, l);
    float* C = selbuf(selC, l);

    __shared__ float As[16][UNITS];
    const int i0 = blockIdx.x * 16;
    const int tid = threadIdx.x;   // = output column j

    for (int e = tid; e < 16 * UNITS; e += 256)
        As[e >> 8][e & 255] = A[(i0 + (e >> 8)) * UNITS + (e & 255)];
    __syncthreads();

    float acc[16];
    #pragma unroll
    for (int i = 0; i < 16; i++) acc[i] = 0.0f;

    for (int k = 0; k < UNITS; k++) {
        const float bv = Bm[k * UNITS + tid];
        #pragma unroll
        for (int i = 0; i < 16; i++) acc[i] += As[i][k] * bv;
    }
    #pragma unroll
    for (int i = 0; i < 16; i++) {
        float rres = acc[i];
        if (mode) rres = (((i0 + i) == tid) ? 2.0f : 0.0f) - rres;
        C[(i0 + i) * UNITS + tid] = rres;
    }
}

// =====================================================================
// 3) Transpose-negate: g_MTn[l] = -(g_M[l])^T
// =====================================================================
__global__ void transneg_kernel() {
    const int l = blockIdx.z;
    __shared__ float t[32][33];
    const int x0 = blockIdx.x * 32, y0 = blockIdx.y * 32;
    const int tx = threadIdx.x, ty = threadIdx.y;   // 32 x 8
    #pragma unroll
    for (int i = 0; i < 32; i += 8)
        t[ty + i][tx] = g_M[l][(y0 + ty + i) * UNITS + x0 + tx];
    __syncthreads();
    #pragma unroll
    for (int i = 0; i < 32; i += 8)
        g_MTn[l][(x0 + ty + i) * UNITS + y0 + tx] = -t[tx][ty + i];
}

// =====================================================================
// 4) Input GEMM: v0 = (x @ W_in + b_in)^T  (stored [UNITS][BATCH]),
//    v1 = tanh(v0).  K = 784.  Tile 128x128, BK=16, 8x8 per thread.
// =====================================================================
#define BMT 128
#define BNT 128
#define BKT 16
#define TSTR 132   // padded smem row stride (keeps 16B alignment: 132*4=528)

__global__ __launch_bounds__(256) void input_gemm_kernel(const float* __restrict__ x,
                                                         const float* __restrict__ Win,
                                                         const float* __restrict__ bin) {
    __shared__ float As[BKT][BMT];    // [k][i] : W_in already k-major
    __shared__ float Vs[BKT][TSTR];   // [k][j] : transposed from x

    const int tid = threadIdx.x;
    const int i0 = blockIdx.y * BMT;
    const int j0 = blockIdx.x * BNT;
    const int rf = (tid >> 4) * 8;
    const int cf = (tid & 15) * 8;

    float acc[8][8];
    #pragma unroll
    for (int r = 0; r < 8; r++)
        #pragma unroll
        for (int c = 0; c < 8; c++) acc[r][c] = 0.0f;

    for (int k0 = 0; k0 < DIN; k0 += BKT) {
        #pragma unroll
        for (int m = 0; m < 2; m++) {
            int f = tid + m * 256;
            // A tile: direct copy (W_in is [k][i])
            int kk = f >> 5, ic = (f & 31) * 4;
            float4 a = *(const float4*)&Win[(k0 + kk) * UNITS + i0 + ic];
            *(float4*)&As[kk][ic] = a;
            // V tile: transpose from x rows
            int jj = f >> 2, kc = (f & 3) * 4;
            float4 xv = *(const float4*)&x[(size_t)(j0 + jj) * DIN + k0 + kc];
            Vs[kc + 0][jj] = xv.x;
            Vs[kc + 1][jj] = xv.y;
            Vs[kc + 2][jj] = xv.z;
            Vs[kc + 3][jj] = xv.w;
        }
        __syncthreads();
        #pragma unroll
        for (int kk = 0; kk < BKT; kk++) {
            float a[8], v[8];
            *(float4*)&a[0] = *(const float4*)&As[kk][rf];
            *(float4*)&a[4] = *(const float4*)&As[kk][rf + 4];
            *(float4*)&v[0] = *(const float4*)&Vs[kk][cf];
            *(float4*)&v[4] = *(const float4*)&Vs[kk][cf + 4];
            #pragma unroll
            for (int r = 0; r < 8; r++)
                #pragma unroll
                for (int c = 0; c < 8; c++) acc[r][c] += a[r] * v[c];
        }
        __syncthreads();
    }

    #pragma unroll
    for (int r = 0; r < 8; r++) {
        const int row = i0 + rf + r;
        const float b = __ldg(&bin[row]);
        const size_t base = (size_t)row * BATCH + j0 + cf;
        #pragma unroll
        for (int c = 0; c < 8; c++) {
            float u = acc[r][c] + b;
            g_v0[0][base + c] = u;
            g_v1[0][base + c] = tanhf(u);
        }
    }
}

// =====================================================================
// 5) Layer GEMM (both products in one launch, blockIdx.z = which):
//    which==0:  v0[nb] = (-M^T) * v1[cb]
//    which==1:  v1[nb] =   M    * (v0[cb] + q_l)
// =====================================================================
__global__ __launch_bounds__(256) void layer_gemm_kernel(const float* __restrict__ qarr,
                                                         int l, int cb) {
    const int which = blockIdx.z;
    const int nb = cb ^ 1;
    const float* A;
    const float* V;
    float* C;
    const float* q = nullptr;
    if (which == 0) { A = g_MTn[l]; V = g_v1[cb]; C = g_v0[nb]; }
    else            { A = g_M[l];   V = g_v0[cb]; C = g_v1[nb]; q = qarr + l * UNITS; }

    __shared__ float As[BKT][TSTR];   // [k][i] transposed from A (row-major [i][k])
    __shared__ float Vs[BKT][TSTR];

    const int tid = threadIdx.x;
    const int i0 = blockIdx.y * BMT;
    const int j0 = blockIdx.x * BNT;
    const int rf = (tid >> 4) * 8;
    const int cf = (tid & 15) * 8;

    float acc[8][8];
    #pragma unroll
    for (int r = 0; r < 8; r++)
        #pragma unroll
        for (int c = 0; c < 8; c++) acc[r][c] = 0.0f;

    for (int k0 = 0; k0 < UNITS; k0 += BKT) {
        #pragma unroll
        for (int m = 0; m < 2; m++) {
            int f = tid + m * 256;
            // A tile: transpose-on-store
            int ii = f >> 2, kc = (f & 3) * 4;
            float4 a = *(const float4*)&A[(i0 + ii) * UNITS + k0 + kc];
            As[kc + 0][ii] = a.x;
            As[kc + 1][ii] = a.y;
            As[kc + 2][ii] = a.z;
            As[kc + 3][ii] = a.w;
            // V tile: direct (row-major [k][j]), optional +q[k]
            int kk = f >> 5, jc = (f & 31) * 4;
            float4 v = *(const float4*)&V[(size_t)(k0 + kk) * BATCH + j0 + jc];
            if (q) {
                float qk = __ldg(&q[k0 + kk]);
                v.x += qk; v.y += qk; v.z += qk; v.w += qk;
            }
            *(float4*)&Vs[kk][jc] = v;
        }
        __syncthreads();
        #pragma unroll
        for (int kk = 0; kk < BKT; kk++) {
            float a[8], v[8];
            *(float4*)&a[0] = *(const float4*)&As[kk][rf];
            *(float4*)&a[4] = *(const float4*)&As[kk][rf + 4];
            *(float4*)&v[0] = *(const float4*)&Vs[kk][cf];
            *(float4*)&v[4] = *(const float4*)&Vs[kk][cf + 4];
            #pragma unroll
            for (int r = 0; r < 8; r++)
                #pragma unroll
                for (int c = 0; c < 8; c++) acc[r][c] += a[r] * v[c];
        }
        __syncthreads();
    }

    #pragma unroll
    for (int r = 0; r < 8; r++) {
        const size_t base = (size_t)(i0 + rf + r) * BATCH + j0 + cf;
        *(float4*)&C[base]     = *(float4*)&acc[r][0];
        *(float4*)&C[base + 4] = *(float4*)&acc[r][4];
    }
}

// =====================================================================
// 6) Output GEMM: out[j][d] = sum_k v0[k][j] * W_out[k][d] + b_out[d]
// =====================================================================
__global__ __launch_bounds__(256) void out_gemm_kernel(const float* __restrict__ Wout,
                                                       const float* __restrict__ bout,
                                                       float* __restrict__ out) {
    __shared__ float Ws[UNITS * DOUT];
    const int tid = threadIdx.x;
    for (int e = tid; e < UNITS * DOUT; e += 256) Ws[e] = Wout[e];
    __syncthreads();

    const int j = blockIdx.x * 256 + tid;
    const float* v = g_v0[0];   // after 6 layers, result is in buffer 0
    float acc[DOUT];
    #pragma unroll
    for (int d = 0; d < DOUT; d++) acc[d] = 0.0f;

    for (int k = 0; k < UNITS; k++) {
        const float val = v[(size_t)k * BATCH + j];
        #pragma unroll
        for (int d = 0; d < DOUT; d++) acc[d] += val * Ws[k * DOUT + d];
    }
    #pragma unroll
    for (int d = 0; d < DOUT; d++)
        out[(size_t)j * DOUT + d] = acc[d] + __ldg(&bout[d]);
}

// =====================================================================
// launch
// =====================================================================
extern "C" void kernel_launch(void* const* d_in, const int* in_sizes, int n_in,
                              void* d_out, int out_size) {
    const float* x    = (const float*)d_in[0];
    const float* Win  = (const float*)d_in[1];
    const float* bin  = (const float*)d_in[2];
    const float* B0   = (const float*)d_in[3];
    const float* q    = (const float*)d_in[4];
    const float* Wout = (const float*)d_in[5];
    const float* bout = (const float*)d_in[6];
    float* out = (float*)d_out;

    // --- invert B0 matrices (GJ, no pivoting) ---
    gj_invert_kernel<<<NLAYERS, 1024>>>(B0);

    // --- 2 Newton-Schulz refinement steps: M <- M (2I - B0 M) ---
    dim3 sg(16, NLAYERS);
    small_gemm_kernel<<<sg, 256>>>(B0, -1, 0, 2, 1);       // R  = 2I - B0*M
    small_gemm_kernel<<<sg, 256>>>(nullptr, 0, 2, 1, 0);   // M2 = M*R
    small_gemm_kernel<<<sg, 256>>>(B0, -1, 1, 2, 1);       // R  = 2I - B0*M2
    small_gemm_kernel<<<sg, 256>>>(nullptr, 1, 2, 0, 0);   // M  = M2*R

    // --- MTn = -M^T ---
    transneg_kernel<<<dim3(8, 8, NLAYERS), dim3(32, 8)>>>();

    // --- input GEMM + tanh ---
    input_gemm_kernel<<<dim3(BATCH / BNT, UNITS / BMT), 256>>>(x, Win, bin);

    // --- 6 layers, both products per launch ---
    for (int l = 0; l < NLAYERS; l++) {
        layer_gemm_kernel<<<dim3(BATCH / BNT, UNITS / BMT, 2), 256>>>(q, l, l & 1);
    }

    // --- output GEMM ---
    out_gemm_kernel<<<BATCH / 256, 256>>>(Wout, bout, out);
}

// round 4
// speedup vs baseline: 1.1325x; 1.1325x over previous
#include <cuda_runtime.h>
#include <cuda_bf16.h>
#include <math.h>
#include <stdint.h>

#define UNITS   256
#define BATCH   32768
#define NLAYERS 6
#define DIN     784
#define KIN     832          // DIN padded to multiple of 64
#define DOUT    10

// ===================== device-global scratch (no runtime allocs) =====================
__device__ float g_M  [NLAYERS][UNITS * UNITS];
__device__ float g_M2 [NLAYERS][UNITS * UNITS];
__device__ float g_R  [NLAYERS][UNITS * UNITS];
__device__ float g_MTn[NLAYERS][UNITS * UNITS];

// bf16x2 split weights: [layer][which 0:-M^T 1:M][split h/m][n][k]
__device__ __nv_bfloat16 g_W   [NLAYERS][2][2][UNITS * UNITS];
// bf16x2 split of x (zero-padded K) and W_in^T ([n][k])
__device__ __nv_bfloat16 g_X   [2][(size_t)BATCH * KIN];
__device__ __nv_bfloat16 g_WinT[2][(size_t)UNITS * KIN];
// activations, [buf][split][batch][unit] row-major
__device__ __nv_bfloat16 g_A0  [2][2][(size_t)BATCH * UNITS];
__device__ __nv_bfloat16 g_A1  [2][2][(size_t)BATCH * UNITS];

// ===================== helpers =====================
__device__ __forceinline__ uint32_t smem_u32(const void* p) {
    uint32_t a;
    asm("{ .reg .u64 t; cvta.to.shared.u64 t, %1; cvt.u32.u64 %0, t; }" : "=r"(a) : "l"(p));
    return a;
}
#define SWZ(o) ((o) ^ (((o) >> 3) & 0x70))

#define CP_ASYNC16(dst, src) \
    asm volatile("cp.async.cg.shared.global [%0], [%1], 16;" :: "r"(dst), "l"(src))
#define CP_COMMIT() asm volatile("cp.async.commit_group;" ::: "memory")
#define CP_WAIT1()  asm volatile("cp.async.wait_group 1;" ::: "memory")
#define CP_WAIT0()  asm volatile("cp.async.wait_group 0;" ::: "memory")

#define LDSM4(r0, r1, r2, r3, a) \
    asm volatile("ldmatrix.sync.aligned.m8n8.x4.shared.b16 {%0,%1,%2,%3}, [%4];" \
                 : "=r"(r0), "=r"(r1), "=r"(r2), "=r"(r3) : "r"(a))

#define MMA16816(c0, c1, c2, c3, a0, a1, a2, a3, b0, b1)                         \
    asm volatile("mma.sync.aligned.m16n8k16.row.col.f32.bf16.bf16.f32 "          \
                 "{%0,%1,%2,%3}, {%4,%5,%6,%7}, {%8,%9}, {%0,%1,%2,%3};"         \
                 : "+f"(c0), "+f"(c1), "+f"(c2), "+f"(c3)                        \
                 : "r"(a0), "r"(a1), "r"(a2), "r"(a3), "r"(b0), "r"(b1))

__device__ __forceinline__ uint32_t pack2(__nv_bfloat16 a, __nv_bfloat16 b) {
    return ((uint32_t)__bfloat16_as_ushort(b) << 16) | (uint32_t)__bfloat16_as_ushort(a);
}
// split x into h (bf16) + m (bf16 of remainder); store 2 consecutive n-elems per split
__device__ __forceinline__ void split2_store(__nv_bfloat16* Dh, __nv_bfloat16* Dm,
                                             size_t off, float x, float y) {
    __nv_bfloat16 hx = __float2bfloat16(x);
    __nv_bfloat16 hy = __float2bfloat16(y);
    __nv_bfloat16 mx = __float2bfloat16(x - __bfloat162float(hx));
    __nv_bfloat16 my = __float2bfloat16(y - __bfloat162float(hy));
    *(uint32_t*)(Dh + off) = pack2(hx, hy);
    *(uint32_t*)(Dm + off) = pack2(mx, my);
}
__device__ __forceinline__ float bflo(uint32_t u) {
    return __bfloat162float(__ushort_as_bfloat16((unsigned short)(u & 0xFFFF)));
}
__device__ __forceinline__ float bfhi(uint32_t u) {
    return __bfloat162float(__ushort_as_bfloat16((unsigned short)(u >> 16)));
}

// =====================================================================
// 1) Gauss-Jordan inversion (no pivoting), one CTA per matrix
// =====================================================================
__global__ __launch_bounds__(1024) void gj_invert_kernel(const float* __restrict__ B0) {
    const int l = blockIdx.x;
    float* S = g_M[l];
    const float* A = B0 + l * UNITS * UNITS;
    const int tid = threadIdx.x;
    for (int i = tid; i < UNITS * UNITS; i += 1024) S[i] = A[i];
    __syncthreads();
    __shared__ float sp[UNITS], sf[UNITS];
    const int r  = tid >> 2;
    const int c0 = (tid & 3) * 64;
    for (int p = 0; p < UNITS; p++) {
        if (tid < UNITS) sf[tid] = S[tid * UNITS + p];
        __syncthreads();
        const float ipiv = 1.0f / sf[p];
        if (tid < UNITS) sp[tid] = (tid == p) ? ipiv : S[p * UNITS + tid] * ipiv;
        __syncthreads();
        if (r == p) {
            float4* dst = (float4*)&S[r * UNITS + c0];
            #pragma unroll
            for (int v = 0; v < 16; v++) {
                float4 w;
                w.x = sp[c0 + 4 * v + 0]; w.y = sp[c0 + 4 * v + 1];
                w.z = sp[c0 + 4 * v + 2]; w.w = sp[c0 + 4 * v + 3];
                dst[v] = w;
            }
        } else {
            const float f = sf[r];
            float4* row = (float4*)&S[r * UNITS + c0];
            #pragma unroll
            for (int v = 0; v < 16; v++) {
                float4 xv = row[v];
                xv.x -= f * sp[c0 + 4 * v + 0]; xv.y -= f * sp[c0 + 4 * v + 1];
                xv.z -= f * sp[c0 + 4 * v + 2]; xv.w -= f * sp[c0 + 4 * v + 3];
                row[v] = xv;
            }
            if (p >= c0 && p < c0 + 64) S[r * UNITS + p] = -f * ipiv;
        }
        __syncthreads();
    }
}

// =====================================================================
// 2) Newton-Schulz GEMM, 128x128 tiles: C = A*B or C = 2I - A*B
// =====================================================================
__device__ __forceinline__ float* selbuf(int s, int l) {
    return (s == 0) ? g_M[l] : (s == 1) ? g_M2[l] : g_R[l];
}
__global__ __launch_bounds__(256) void newton_gemm_kernel(const float* __restrict__ Aext,
                                                          int selA, int selB, int selC, int mode) {
    const int l = blockIdx.z;
    const float* A  = (selA < 0) ? (Aext + l * UNITS * UNITS) : selbuf(selA, l);
    const float* Bm = selbuf(selB, l);
    float* C = selbuf(selC, l);
    __shared__ float As[16][132], Bs[16][132];
    const int tid = threadIdx.x;
    const int i0 = blockIdx.y * 128, j0 = blockIdx.x * 128;
    const int rf = (tid >> 4) * 8, cf = (tid & 15) * 8;
    float acc[8][8];
    #pragma unroll
    for (int r = 0; r < 8; r++)
        #pragma unroll
        for (int c = 0; c < 8; c++) acc[r][c] = 0.0f;
    for (int k0 = 0; k0 < UNITS; k0 += 16) {
        #pragma unroll
        for (int m = 0; m < 2; m++) {
            int f = tid + m * 256;
            int ii = f >> 2, kc = (f & 3) * 4;
            float4 a = *(const float4*)&A[(i0 + ii) * UNITS + k0 + kc];
            As[kc + 0][ii] = a.x; As[kc + 1][ii] = a.y; As[kc + 2][ii] = a.z; As[kc + 3][ii] = a.w;
            int kk = f >> 5, jc = (f & 31) * 4;
            *(float4*)&Bs[kk][jc] = *(const float4*)&Bm[(k0 + kk) * UNITS + j0 + jc];
        }
        __syncthreads();
        #pragma unroll
        for (int kk = 0; kk < 16; kk++) {
            float a[8], b[8];
            *(float4*)&a[0] = *(const float4*)&As[kk][rf];
            *(float4*)&a[4] = *(const float4*)&As[kk][rf + 4];
            *(float4*)&b[0] = *(const float4*)&Bs[kk][cf];
            *(float4*)&b[4] = *(const float4*)&Bs[kk][cf + 4];
            #pragma unroll
            for (int r = 0; r < 8; r++)
                #pragma unroll
                for (int c = 0; c < 8; c++) acc[r][c] += a[r] * b[c];
        }
        __syncthreads();
    }
    #pragma unroll
    for (int r = 0; r < 8; r++) {
        int i = i0 + rf + r;
        #pragma unroll
        for (int c = 0; c < 8; c++) {
            int j = j0 + cf + c;
            float v = acc[r][c];
            if (mode) v = ((i == j) ? 2.0f : 0.0f) - v;
            C[i * UNITS + j] = v;
        }
    }
}

// =====================================================================
// 3) g_MTn = -(g_M)^T
// =====================================================================
__global__ void transneg_kernel() {
    const int l = blockIdx.z;
    __shared__ float t[32][33];
    const int x0 = blockIdx.x * 32, y0 = blockIdx.y * 32;
    const int tx = threadIdx.x, ty = threadIdx.y;
    #pragma unroll
    for (int i = 0; i < 32; i += 8)
        t[ty + i][tx] = g_M[l][(y0 + ty + i) * UNITS + x0 + tx];
    __syncthreads();
    #pragma unroll
    for (int i = 0; i < 32; i += 8)
        g_MTn[l][(x0 + ty + i) * UNITS + y0 + tx] = -t[tx][ty + i];
}

// =====================================================================
// 4) split kernels (bf16x2)
// =====================================================================
__global__ __launch_bounds__(256) void split_weights_kernel() {
    const int l = blockIdx.z, which = blockIdx.y;
    const float* src = which ? g_M[l] : g_MTn[l];
    const int e = blockIdx.x * 256 + threadIdx.x;
    float v = src[e];
    __nv_bfloat16 h = __float2bfloat16(v);
    __nv_bfloat16 m = __float2bfloat16(v - __bfloat162float(h));
    g_W[l][which][0][e] = h;
    g_W[l][which][1][e] = m;
}

__global__ __launch_bounds__(256) void split_x_kernel(const float* __restrict__ x) {
    const int idx = blockIdx.x * 256 + threadIdx.x;     // BATCH * (KIN/4) threads
    const int j = idx / (KIN / 4);
    const int k = (idx % (KIN / 4)) * 4;
    float4 v = make_float4(0.f, 0.f, 0.f, 0.f);
    if (k < DIN) v = *(const float4*)(x + (size_t)j * DIN + k);
    float vv[4] = {v.x, v.y, v.z, v.w};
    __nv_bfloat16 h[4], m[4];
    #pragma unroll
    for (int e = 0; e < 4; e++) {
        h[e] = __float2bfloat16(vv[e]);
        m[e] = __float2bfloat16(vv[e] - __bfloat162float(h[e]));
    }
    const size_t off = (size_t)j * KIN + k;
    *(uint2*)(&g_X[0][off]) = make_uint2(pack2(h[0], h[1]), pack2(h[2], h[3]));
    *(uint2*)(&g_X[1][off]) = make_uint2(pack2(m[0], m[1]), pack2(m[2], m[3]));
}

__global__ __launch_bounds__(256) void split_winT_kernel(const float* __restrict__ Win) {
    const int e = blockIdx.x * 256 + threadIdx.x;       // UNITS*KIN threads
    const int n = e / KIN, k = e % KIN;
    float v = (k < DIN) ? Win[(size_t)k * UNITS + n] : 0.0f;
    __nv_bfloat16 h = __float2bfloat16(v);
    __nv_bfloat16 m = __float2bfloat16(v - __bfloat162float(h));
    g_WinT[0][e] = h;
    g_WinT[1][e] = m;
}

// =====================================================================
// 5) HMMA (mma.sync bf16) GEMM with bf16x2 x 3-product split.
//    D[j,n] = sum_k A[j,k] * W[n,k]
//    mode 0: input GEMM (K=KIN): u=D+bin[n]; A0[0]=split(u+q0), A1[0]=split(tanh u)
//    mode 1: layer GEMM (K=256), blockIdx.z=which:
//       which==1: v1' = M*(act0[cb])      -> A1[nb]
//       which==0: v0' = (-M^T)*act1[cb]   -> A0[nb] (+ q[l+1] baked if l<5)
// =====================================================================
#define BK      64
#define ATILE_B 16384                 // 128 x 64 bf16
#define STAGE_B 32768                 // A + B per stage
#define HS_BYTES (2 * STAGE_B)        // 64 KB double-buffered

__global__ __launch_bounds__(256, 2) void hmma_gemm_kernel(int mode, int l, int cb,
                                                           const float* __restrict__ bin,
                                                           const float* __restrict__ q) {
    extern __shared__ char smem[];
    const uint32_t sb = smem_u32(smem);
    const int tid  = threadIdx.x;
    const int lane = tid & 31;
    const int wid  = tid >> 5;
    const int warpM = (wid >> 1) * 32;
    const int warpN = (wid & 1) * 64;
    const int which = (mode == 0) ? 1 : blockIdx.z;   // input GEMM acts like "compute"
    const int j0 = blockIdx.x * 128;
    const int n0 = blockIdx.y * 128;
    const int KC   = (mode == 0) ? (KIN / BK) : (UNITS / BK);
    const int arow = (mode == 0) ? KIN : UNITS;
    const int NC = 3 * KC;

    // product operand selection: t 0:(Ah,Wh) 1:(Ah,Wm) 2:(Am,Wh)
    const __nv_bfloat16* Ah;
    const __nv_bfloat16* Am;
    const __nv_bfloat16* Wh;
    const __nv_bfloat16* Wm;
    if (mode == 0) {
        Ah = g_X[0]; Am = g_X[1]; Wh = g_WinT[0]; Wm = g_WinT[1];
    } else {
        Ah = which ? &g_A0[cb][0][0] : &g_A1[cb][0][0];
        Am = which ? &g_A0[cb][1][0] : &g_A1[cb][1][0];
        Wh = &g_W[l][which][0][0];
        Wm = &g_W[l][which][1][0];
    }

    // per-thread load slots: 4 x 16B for A, 4 x 16B for B per chunk
    const int lr = tid >> 1;            // 0..127 row
    const int lc = (tid & 1) * 4;       // col group base (x4 iterations add +0..3? no: see below)
    (void)lr; (void)lc;

    float acc[2][8][4];
    #pragma unroll
    for (int mt = 0; mt < 2; mt++)
        #pragma unroll
        for (int nt = 0; nt < 8; nt++)
            #pragma unroll
            for (int e = 0; e < 4; e++) acc[mt][nt][e] = 0.0f;

    // ---- issue loads for chunk ch into stage st ----
    auto issue = [&](int ch, int st) {
        int t = ch / KC, kc = ch - t * KC;
        const __nv_bfloat16* Ab = (t == 2) ? Am : Ah;
        const __nv_bfloat16* Wb = (t == 1) ? Wm : Wh;
        const int k0 = kc * BK;
        const uint32_t sa  = sb + st * STAGE_B;
        const uint32_t sbm = sa + ATILE_B;
        #pragma unroll
        for (int i = 0; i < 4; i++) {
            int idx = tid + i * 256;          // 0..1023
            int r = idx >> 3, c = idx & 7;
            uint32_t soff = SWZ(r * 128 + c * 16);
            CP_ASYNC16(sa  + soff, Ab + (size_t)(j0 + r) * arow + k0 + c * 8);
            CP_ASYNC16(sbm + soff, Wb + (size_t)(n0 + r) * arow + k0 + c * 8);
        }
        CP_COMMIT();
    };

    issue(0, 0);
    for (int ch = 0; ch < NC; ch++) {
        if (ch + 1 < NC) { issue(ch + 1, (ch + 1) & 1); CP_WAIT1(); }
        else             { CP_WAIT0(); }
        __syncthreads();

        const uint32_t sa  = sb + (ch & 1) * STAGE_B;
        const uint32_t sbm = sa + ATILE_B;
        #pragma unroll
        for (int kt = 0; kt < BK / 16; kt++) {
            uint32_t ra[2][4], rb[4][4];
            const int koff = kt * 32 + ((lane >> 4) & 1) * 16;
            #pragma unroll
            for (int mt = 0; mt < 2; mt++) {
                uint32_t a = sa + SWZ((warpM + mt * 16 + (lane & 15)) * 128 + koff);
                LDSM4(ra[mt][0], ra[mt][1], ra[mt][2], ra[mt][3], a);
            }
            #pragma unroll
            for (int bt = 0; bt < 4; bt++) {
                uint32_t a = sbm + SWZ((warpN + bt * 16 + (lane & 15)) * 128 + koff);
                LDSM4(rb[bt][0], rb[bt][1], rb[bt][2], rb[bt][3], a);
            }
            #pragma unroll
            for (int mt = 0; mt < 2; mt++)
                #pragma unroll
                for (int nt = 0; nt < 8; nt++) {
                    const int bt = nt >> 1, hi = nt & 1;
                    MMA16816(acc[mt][nt][0], acc[mt][nt][1], acc[mt][nt][2], acc[mt][nt][3],
                             ra[mt][0], ra[mt][1], ra[mt][2], ra[mt][3],
                             rb[bt][hi], rb[bt][2 + hi]);
                }
        }
        __syncthreads();
    }

    // ---------------- epilogue ----------------
    __nv_bfloat16 *D0h, *D0m, *D1h = nullptr, *D1m = nullptr;
    const float* qp = nullptr;
    if (mode == 0) {
        D0h = &g_A0[0][0][0]; D0m = &g_A0[0][1][0];
        D1h = &g_A1[0][0][0]; D1m = &g_A1[0][1][0];
        qp = q;                                     // q layer 0
    } else {
        const int nb = cb ^ 1;
        if (which) { D0h = &g_A1[nb][0][0]; D0m = &g_A1[nb][1][0]; }
        else {
            D0h = &g_A0[nb][0][0]; D0m = &g_A0[nb][1][0];
            if (l < NLAYERS - 1) qp = q + (l + 1) * UNITS;
        }
    }

    const int rbase = lane >> 2;
    const int cbase = (lane & 3) * 2;
    #pragma unroll
    for (int mt = 0; mt < 2; mt++) {
        #pragma unroll
        for (int half = 0; half < 2; half++) {
            const int j = j0 + warpM + mt * 16 + rbase + half * 8;
            const size_t ob = (size_t)j * UNITS;
            #pragma unroll
            for (int nt = 0; nt < 8; nt++) {
                const int n = n0 + warpN + nt * 8 + cbase;
                float v0 = acc[mt][nt][half * 2 + 0];
                float v1 = acc[mt][nt][half * 2 + 1];
                if (mode == 0) {
                    float u0 = v0 + bin[n], u1 = v1 + bin[n + 1];
                    split2_store(D0h, D0m, ob + n, u0 + qp[n], u1 + qp[n + 1]);
                    split2_store(D1h, D1m, ob + n, tanhf(u0), tanhf(u1));
                } else {
                    if (qp) { v0 += qp[n]; v1 += qp[n + 1]; }
                    split2_store(D0h, D0m, ob + n, v0, v1);
                }
            }
        }
    }
}

// =====================================================================
// 6) output GEMM: out[j][d] = sum_k (h+m)(act0[j][k]) * Wout[k][d] + bout[d]
// =====================================================================
__global__ __launch_bounds__(256) void out_gemm_kernel(const float* __restrict__ Wout,
                                                       const float* __restrict__ bout,
                                                       float* __restrict__ out) {
    __shared__ float Ws[UNITS * DOUT];
    const int tid = threadIdx.x;
    for (int e = tid; e < UNITS * DOUT; e += 256) Ws[e] = Wout[e];
    __syncthreads();
    const size_t j = (size_t)blockIdx.x * 256 + tid;
    const size_t base = j * UNITS;
    const __nv_bfloat16* ph = &g_A0[0][0][0];
    const __nv_bfloat16* pm = &g_A0[0][1][0];
    float acc[DOUT];
    #pragma unroll
    for (int d = 0; d < DOUT; d++) acc[d] = 0.0f;
    for (int k0 = 0; k0 < UNITS; k0 += 8) {
        uint4 uh = *(const uint4*)(ph + base + k0);
        uint4 um = *(const uint4*)(pm + base + k0);
        uint32_t wh[4] = {uh.x, uh.y, uh.z, uh.w};
        uint32_t wm[4] = {um.x, um.y, um.z, um.w};
        #pragma unroll
        for (int p = 0; p < 4; p++) {
            float v0 = bflo(wh[p]) + bflo(wm[p]);
            float v1 = bfhi(wh[p]) + bfhi(wm[p]);
            const int k = k0 + p * 2;
            #pragma unroll
            for (int d = 0; d < DOUT; d++) {
                acc[d] += v0 * Ws[k * DOUT + d];
                acc[d] += v1 * Ws[(k + 1) * DOUT + d];
            }
        }
    }
    #pragma unroll
    for (int d = 0; d < DOUT; d++)
        out[j * DOUT + d] = acc[d] + __ldg(&bout[d]);
}

// =====================================================================
// launch
// =====================================================================
extern "C" void kernel_launch(void* const* d_in, const int* in_sizes, int n_in,
                              void* d_out, int out_size) {
    const float* x    = (const float*)d_in[0];
    const float* Win  = (const float*)d_in[1];
    const float* bin  = (const float*)d_in[2];
    const float* B0   = (const float*)d_in[3];
    const float* q    = (const float*)d_in[4];
    const float* Wout = (const float*)d_in[5];
    const float* bout = (const float*)d_in[6];
    float* out = (float*)d_out;

    cudaFuncSetAttribute(hmma_gemm_kernel, cudaFuncAttributeMaxDynamicSharedMemorySize, HS_BYTES);

    // inversion + Newton refinement
    gj_invert_kernel<<<NLAYERS, 1024>>>(B0);
    dim3 ng(2, 2, NLAYERS);
    newton_gemm_kernel<<<ng, 256>>>(B0, -1, 0, 2, 1);       // R  = 2I - B0*M
    newton_gemm_kernel<<<ng, 256>>>(nullptr, 0, 2, 1, 0);   // M2 = M*R
    newton_gemm_kernel<<<ng, 256>>>(B0, -1, 1, 2, 1);       // R  = 2I - B0*M2
    newton_gemm_kernel<<<ng, 256>>>(nullptr, 1, 2, 0, 0);   // M  = M2*R
    transneg_kernel<<<dim3(8, 8, NLAYERS), dim3(32, 8)>>>();

    // bf16x2 splits
    split_weights_kernel<<<dim3(UNITS * UNITS / 256, 2, NLAYERS), 256>>>();
    split_x_kernel<<<(BATCH * (KIN / 4)) / 256, 256>>>(x);
    split_winT_kernel<<<(UNITS * KIN) / 256, 256>>>(Win);

    // input GEMM (tensor cores via mma.sync)
    hmma_gemm_kernel<<<dim3(BATCH / 128, 2, 1), 256, HS_BYTES>>>(0, 0, 0, bin, q);

    // 6 layers, both products per launch (z = which)
    for (int l = 0; l < NLAYERS; l++)
        hmma_gemm_kernel<<<dim3(BATCH / 128, 2, 2), 256, HS_BYTES>>>(1, l, l & 1, bin, q);

    // output GEMM
    out_gemm_kernel<<<BATCH / 256, 256>>>(Wout, bout, out);
}

// round 5
// speedup vs baseline: 1.2083x; 1.0669x over previous
#include <cuda_runtime.h>
#include <math.h>
#include <stdint.h>

#define U     256
#define SZ    65536          // U*U
#define BATCH 32768
#define NL    6
#define DIN   784
#define DOUT  10

// ===================== device-global scratch (no runtime allocs) =====================
__device__ float g_M  [NL][SZ];
__device__ float g_M2 [NL][SZ];
__device__ float g_R  [NL][SZ];
__device__ float g_MTn[NL][SZ];
__device__ float g_CX [2][SZ];       // chain ping-pong: top-row block
__device__ float g_CY [2][SZ];       // chain ping-pong: bottom-row block
__device__ float g_c  [2][2 * U];    // constant chain [buf][c0|c1]
__device__ float g_G  [DOUT * U];    // G = Wout^T * K   (10 x 256)
__device__ float g_F  [DIN * DOUT];  // F stored [k][d]  (784 x 10)
__device__ float g_f  [16];          // f (10) padded

// =====================================================================
// 1) Gauss-Jordan inversion (no pivoting), one CTA per matrix -> g_M
// =====================================================================
__global__ __launch_bounds__(1024) void gj_invert_kernel(const float* __restrict__ B0) {
    const int l = blockIdx.x;
    float* S = g_M[l];
    const float* A = B0 + l * SZ;
    const int tid = threadIdx.x;
    for (int i = tid; i < SZ; i += 1024) S[i] = A[i];
    __syncthreads();
    __shared__ float sp[U], sf[U];
    const int r  = tid >> 2;
    const int c0 = (tid & 3) * 64;
    for (int p = 0; p < U; p++) {
        if (tid < U) sf[tid] = S[tid * U + p];
        __syncthreads();
        const float ipiv = 1.0f / sf[p];
        if (tid < U) sp[tid] = (tid == p) ? ipiv : S[p * U + tid] * ipiv;
        __syncthreads();
        if (r == p) {
            float4* dst = (float4*)&S[r * U + c0];
            #pragma unroll
            for (int v = 0; v < 16; v++) {
                float4 w;
                w.x = sp[c0 + 4 * v + 0]; w.y = sp[c0 + 4 * v + 1];
                w.z = sp[c0 + 4 * v + 2]; w.w = sp[c0 + 4 * v + 3];
                dst[v] = w;
            }
        } else {
            const float f = sf[r];
            float4* row = (float4*)&S[r * U + c0];
            #pragma unroll
            for (int v = 0; v < 16; v++) {
                float4 xv = row[v];
                xv.x -= f * sp[c0 + 4 * v + 0]; xv.y -= f * sp[c0 + 4 * v + 1];
                xv.z -= f * sp[c0 + 4 * v + 2]; xv.w -= f * sp[c0 + 4 * v + 3];
                row[v] = xv;
            }
            if (p >= c0 && p < c0 + 64) S[r * U + p] = -f * ipiv;
        }
        __syncthreads();
    }
}

// =====================================================================
// 2) shared 64x64-tile fp32 GEMM body over K=256 (C = A*B or 2I - A*B)
// =====================================================================
__device__ __forceinline__ void gemm64_body(const float* __restrict__ A,
                                            const float* __restrict__ Bm,
                                            float* __restrict__ C, int mode,
                                            int bx, int by) {
    __shared__ float As[32][68], Bs[32][68];
    const int tid = threadIdx.x;
    const int i0 = by * 64, j0 = bx * 64;
    const int rf = (tid >> 4) * 4, cf = (tid & 15) * 4;
    float acc[4][4];
    #pragma unroll
    for (int r = 0; r < 4; r++)
        #pragma unroll
        for (int c = 0; c < 4; c++) acc[r][c] = 0.0f;

    for (int k0 = 0; k0 < U; k0 += 32) {
        #pragma unroll
        for (int m = 0; m < 2; m++) {
            int s = tid + m * 256;
            int ii = s >> 3, kc = (s & 7) * 4;
            float4 a = *(const float4*)&A[(i0 + ii) * U + k0 + kc];
            As[kc + 0][ii] = a.x; As[kc + 1][ii] = a.y;
            As[kc + 2][ii] = a.z; As[kc + 3][ii] = a.w;
            int kk = s >> 4, jc = (s & 15) * 4;
            *(float4*)&Bs[kk][jc] = *(const float4*)&Bm[(k0 + kk) * U + j0 + jc];
        }
        __syncthreads();
        #pragma unroll
        for (int kk = 0; kk < 32; kk++) {
            float4 a4 = *(const float4*)&As[kk][rf];
            float4 b4 = *(const float4*)&Bs[kk][cf];
            float av[4] = {a4.x, a4.y, a4.z, a4.w};
            float bv[4] = {b4.x, b4.y, b4.z, b4.w};
            #pragma unroll
            for (int r = 0; r < 4; r++)
                #pragma unroll
                for (int c = 0; c < 4; c++) acc[r][c] += av[r] * bv[c];
        }
        __syncthreads();
    }
    #pragma unroll
    for (int r = 0; r < 4; r++) {
        int i = i0 + rf + r;
        #pragma unroll
        for (int c = 0; c < 4; c++) {
            int j = j0 + cf + c;
            float v = acc[r][c];
            if (mode) v = ((i == j) ? 2.0f : 0.0f) - v;
            C[i * U + j] = v;
        }
    }
}

// Newton GEMM: per-layer stride SZ on all operands (grid z = layer)
__global__ __launch_bounds__(256) void newton64_kernel(const float* __restrict__ A,
                                                       const float* __restrict__ Bm,
                                                       float* __restrict__ C, int mode) {
    const int l = blockIdx.z;
    gemm64_body(A + (size_t)l * SZ, Bm + (size_t)l * SZ, C + (size_t)l * SZ,
                mode, blockIdx.x, blockIdx.y);
}

// Chain step: z=0 -> Xout = MTn_l * Yin ; z=1 -> Yout = M_l * Xin
__global__ __launch_bounds__(256) void chain64_kernel(const float* __restrict__ MTnl,
                                                      const float* __restrict__ Ml,
                                                      const float* __restrict__ Xin,
                                                      const float* __restrict__ Yin,
                                                      float* __restrict__ Xout,
                                                      float* __restrict__ Yout) {
    if (blockIdx.z == 0) gemm64_body(MTnl, Yin, Xout, 0, blockIdx.x, blockIdx.y);
    else                 gemm64_body(Ml,   Xin, Yout, 0, blockIdx.x, blockIdx.y);
}

// =====================================================================
// 3) g_MTn = -(g_M)^T
// =====================================================================
__global__ void transneg_kernel() {
    const int l = blockIdx.z;
    __shared__ float t[32][33];
    const int x0 = blockIdx.x * 32, y0 = blockIdx.y * 32;
    const int tx = threadIdx.x, ty = threadIdx.y;
    #pragma unroll
    for (int i = 0; i < 32; i += 8)
        t[ty + i][tx] = g_M[l][(y0 + ty + i) * U + x0 + tx];
    __syncthreads();
    #pragma unroll
    for (int i = 0; i < 32; i += 8)
        g_MTn[l][(x0 + ty + i) * U + y0 + tx] = -t[tx][ty + i];
}

// =====================================================================
// 4) chain init: CX0 = MTn[0], CY0 = M[0]; zero const buffers
// =====================================================================
__global__ __launch_bounds__(256) void chain_init_kernel() {
    const int s = blockIdx.x * 256 + threadIdx.x;     // 0..16383 float4 slots
    ((float4*)g_CX[0])[s] = ((const float4*)g_MTn[0])[s];
    ((float4*)g_CY[0])[s] = ((const float4*)g_M[0])[s];
    if (s < 256) ((float4*)g_c)[s] = make_float4(0.f, 0.f, 0.f, 0.f);
}

// =====================================================================
// 5) constant chain: c0' = MTn_l*c1 ; c1' = M_l*(c0+q_l)
// =====================================================================
__global__ __launch_bounds__(256) void constmv_kernel(const float* __restrict__ MTnl,
                                                      const float* __restrict__ Ml,
                                                      const float* __restrict__ cin,
                                                      float* __restrict__ cout,
                                                      const float* __restrict__ ql) {
    __shared__ float rs[U];
    const int n = threadIdx.x;
    const int b = blockIdx.x;
    rs[n] = b ? (cin[n] + ql[n]) : cin[U + n];
    __syncthreads();
    const float* A = b ? Ml : MTnl;
    float acc = 0.0f;
    #pragma unroll 8
    for (int m = 0; m < U; m++) acc += A[n * U + m] * rs[m];
    cout[b * U + n] = acc;
}

// =====================================================================
// 6) foldG: G[d][m] = sum_n Wout[n][d] * K[n][m];  f = G*b_in + Wout^T c0 + bout
// =====================================================================
__global__ __launch_bounds__(256) void foldG_kernel(const float* __restrict__ Wout,
                                                    const float* __restrict__ K,
                                                    const float* __restrict__ c0,
                                                    const float* __restrict__ bin,
                                                    const float* __restrict__ bout) {
    __shared__ float Ws[U * DOUT];
    __shared__ float Gs[DOUT][U];
    const int m = threadIdx.x;
    for (int e = m; e < U * DOUT; e += 256) Ws[e] = Wout[e];
    __syncthreads();
    float acc[DOUT];
    #pragma unroll
    for (int d = 0; d < DOUT; d++) acc[d] = 0.0f;
    for (int n = 0; n < U; n++) {
        const float xv = K[n * U + m];
        #pragma unroll
        for (int d = 0; d < DOUT; d++) acc[d] += Ws[n * DOUT + d] * xv;
    }
    #pragma unroll
    for (int d = 0; d < DOUT; d++) { g_G[d * U + m] = acc[d]; Gs[d][m] = acc[d]; }
    __syncthreads();
    if (m < DOUT) {
        float f = bout[m];
        for (int e = 0; e < U; e++) f += Gs[m][e] * bin[e];
        for (int n = 0; n < U; n++) f += Ws[n * DOUT + m] * c0[n];
        g_f[m] = f;
    }
}

// =====================================================================
// 7) foldF: F[k][d] = sum_m G[d][m] * Win[k][m]
// =====================================================================
__global__ __launch_bounds__(256) void foldF_kernel(const float* __restrict__ Win) {
    __shared__ float Gs[DOUT * U];
    const int tid = threadIdx.x;
    for (int e = tid; e < DOUT * U; e += 256) Gs[e] = g_G[e];
    __syncthreads();
    const int k = blockIdx.x * 256 + tid;
    if (k >= DIN) return;
    float acc[DOUT];
    #pragma unroll
    for (int d = 0; d < DOUT; d++) acc[d] = 0.0f;
    for (int m = 0; m < U; m++) {
        const float w = Win[(size_t)k * U + m];
        #pragma unroll
        for (int d = 0; d < DOUT; d++) acc[d] += Gs[d * U + m] * w;
    }
    #pragma unroll
    for (int d = 0; d < DOUT; d++) g_F[k * DOUT + d] = acc[d];
}

// =====================================================================
// 8) final: out[j][:] = F * x[j][:] + f   (10 x 784 affine map)
//    256 CTAs x 128 threads; each warp owns 32 batch rows.
// =====================================================================
__global__ __launch_bounds__(128) void final_kernel(const float* __restrict__ x,
                                                    float* __restrict__ out) {
    __shared__ float Fs[DIN * DOUT];
    __shared__ float fsv[16];
    __shared__ float xs[4][16 * 33];
    const int tid = threadIdx.x;
    for (int e = tid; e < DIN * DOUT; e += 128) Fs[e] = g_F[e];
    if (tid < DOUT) fsv[tid] = g_f[tid];
    __syncthreads();

    const int w = tid >> 5, lane = tid & 31;
    const int row0 = blockIdx.x * 128 + w * 32;
    float* xw = xs[w];
    float acc[DOUT];
    #pragma unroll
    for (int d = 0; d < DOUT; d++) acc[d] = fsv[d];

    for (int k0 = 0; k0 < DIN; k0 += 16) {
        #pragma unroll
        for (int i = 0; i < 4; i++) {
            const int s = lane + 32 * i;
            const int r = s >> 2, kc = (s & 3) * 4;
            float4 v = *(const float4*)&x[(size_t)(row0 + r) * DIN + k0 + kc];
            xw[(kc + 0) * 33 + r] = v.x;
            xw[(kc + 1) * 33 + r] = v.y;
            xw[(kc + 2) * 33 + r] = v.z;
            xw[(kc + 3) * 33 + r] = v.w;
        }
        __syncwarp();
        #pragma unroll
        for (int kk = 0; kk < 16; kk++) {
            const float xv = xw[kk * 33 + lane];
            const float* Fp = &Fs[(k0 + kk) * DOUT];
            #pragma unroll
            for (int d = 0; d < DOUT; d++) acc[d] += xv * Fp[d];
        }
        __syncwarp();
    }
    const size_t j = (size_t)row0 + lane;
    #pragma unroll
    for (int d = 0; d < DOUT; d++) out[j * DOUT + d] = acc[d];
}

// =====================================================================
// launch
// =====================================================================
extern "C" void kernel_launch(void* const* d_in, const int* in_sizes, int n_in,
                              void* d_out, int out_size) {
    const float* x    = (const float*)d_in[0];
    const float* Win  = (const float*)d_in[1];
    const float* bin  = (const float*)d_in[2];
    const float* B0   = (const float*)d_in[3];
    const float* q    = (const float*)d_in[4];
    const float* Wout = (const float*)d_in[5];
    const float* bout = (const float*)d_in[6];
    float* out = (float*)d_out;

    float *pM, *pM2, *pR, *pMTn, *pCX, *pCY, *pc;
    cudaGetSymbolAddress((void**)&pM,   g_M);
    cudaGetSymbolAddress((void**)&pM2,  g_M2);
    cudaGetSymbolAddress((void**)&pR,   g_R);
    cudaGetSymbolAddress((void**)&pMTn, g_MTn);
    cudaGetSymbolAddress((void**)&pCX,  g_CX);
    cudaGetSymbolAddress((void**)&pCY,  g_CY);
    cudaGetSymbolAddress((void**)&pc,   g_c);

    // --- invert B0 (GJ, no pivot) + 2 Newton-Schulz refinement steps ---
    gj_invert_kernel<<<NL, 1024>>>(B0);
    dim3 ng(4, 4, NL);
    newton64_kernel<<<ng, 256>>>(B0, pM, pR, 1);    // R  = 2I - B0*M
    newton64_kernel<<<ng, 256>>>(pM, pR, pM2, 0);   // M2 = M*R
    newton64_kernel<<<ng, 256>>>(B0, pM2, pR, 1);   // R  = 2I - B0*M2
    newton64_kernel<<<ng, 256>>>(pM2, pR, pM, 0);   // M  = M2*R
    transneg_kernel<<<dim3(8, 8, NL), dim3(32, 8)>>>();

    // --- compose K = MTn6*M5*MTn4*M3*MTn2*M1 via X/Y chain ---
    chain_init_kernel<<<64, 256>>>();               // X=MTn[0], Y=M[0], c=0
    for (int l = 1; l < NL; l++) {
        const int cb = (l - 1) & 1, nb = l & 1;
        chain64_kernel<<<dim3(4, 4, 2), 256>>>(
            pMTn + (size_t)l * SZ, pM + (size_t)l * SZ,
            pCX + (size_t)cb * SZ, pCY + (size_t)cb * SZ,
            pCX + (size_t)nb * SZ, pCY + (size_t)nb * SZ);
    }
    // --- constant chain (6 steps); final c0 lands in buffer 0 ---
    for (int l = 0; l < NL; l++) {
        const int cb = l & 1, nb = (l + 1) & 1;
        constmv_kernel<<<2, 256>>>(pMTn + (size_t)l * SZ, pM + (size_t)l * SZ,
                                   pc + cb * 2 * U, pc + nb * 2 * U, q + l * U);
    }

    // --- fold everything into F (10x784) and f (10) ---
    foldG_kernel<<<1, 256>>>(Wout, pCX + SZ /* final X in buf1 */, pc /* c0 buf0 */,
                             bin, bout);
    foldF_kernel<<<4, 256>>>(Win);

    // --- single memory-bound pass over x ---
    final_kernel<<<BATCH / 128, 128>>>(x, out);
}

// round 9
// speedup vs baseline: 6.9634x; 5.7628x over previous
#include <cuda_runtime.h>
#include <math.h>
#include <stdint.h>

#define U     256
#define SZ    65536          // U*U
#define BATCH 32768
#define NL    6
#define DIN   784
#define DOUT  10
#define NB    32             // panel width

// ===================== device-global scratch (no runtime allocs) =====================
__device__ float g_M   [NL][SZ];      // working matrix -> B0^-1
__device__ float g_M2  [NL][SZ];      // Newton temp
__device__ float g_R   [NL][SZ];      // Newton temp
__device__ float g_MTn [NL][SZ];
__device__ float g_Mul [NL][U * NB];  // multipliers of current block step
__device__ float g_ipiv[NL][U];       // 1/pivot per global step
__device__ float g_CX  [2][SZ];       // chain ping-pong
__device__ float g_CY  [2][SZ];
__device__ float g_c   [2][2 * U];    // constant chain [buf][c0|c1]
__device__ float g_G   [DOUT * U];
__device__ float g_F   [DIN * DOUT];
__device__ float g_f   [16];

// =====================================================================
// 0) g_M = B0  (fresh copy each replay)
// =====================================================================
__global__ __launch_bounds__(256) void copyM_kernel(const float* __restrict__ B0) {
    const size_t i = (size_t)blockIdx.x * 256 + threadIdx.x;
    ((float4*)g_M)[i] = ((const float4*)B0)[i];
}

// =====================================================================
// 1a) Panel factorization: scalar GJ steps on the 256xNB panel in smem.
//     EXACT same elimination sequence as the proven monolithic GJ,
//     restricted to the panel columns. Records multipliers + 1/pivots.
//     One CTA per layer, 256 threads = one row each.
// =====================================================================
__global__ __launch_bounds__(256) void panelA_kernel(int kb) {
    __shared__ float P[U * (NB + 1)];   // 256 x 33 (padded)
    __shared__ float sf[U];             // snapshot of panel column p
    __shared__ float sp[NB];            // scaled pivot row (panel cols)
    const int l = blockIdx.x;
    const int r = threadIdx.x;          // row
    float* S = g_M[l];
    const int c0 = kb * NB;

    #pragma unroll
    for (int c = 0; c < NB; c++) P[r * (NB + 1) + c] = S[r * U + c0 + c];
    __syncthreads();

    for (int p = 0; p < NB; p++) {
        const int gp = c0 + p;          // global pivot row
        sf[r] = P[r * (NB + 1) + p];    // snapshot column p BEFORE updates
        __syncthreads();
        const float ipiv = 1.0f / sf[gp];
        if (r < NB) sp[r] = (r == p) ? ipiv : P[gp * (NB + 1) + r] * ipiv;
        if (r == 0) g_ipiv[l][gp] = ipiv;
        __syncthreads();
        const float f = sf[r];
        g_Mul[l][r * NB + p] = f;       // multiplier used at this step
        if (r == gp) {
            #pragma unroll
            for (int c = 0; c < NB; c++) P[r * (NB + 1) + c] = sp[c];
        } else {
            #pragma unroll
            for (int c = 0; c < NB; c++) P[r * (NB + 1) + c] -= f * sp[c];
            P[r * (NB + 1) + p] = -f * ipiv;
        }
        __syncthreads();
    }

    #pragma unroll
    for (int c = 0; c < NB; c++) S[r * U + c0 + c] = P[r * (NB + 1) + c];
}

// =====================================================================
// 1b) Outside-column update: replay the same NB sequential rank-1 row
//     ops on one 256xNB tile (register-resident). grid (7 tiles, NL).
// =====================================================================
__global__ __launch_bounds__(256) void panelB_kernel(int kb) {
    __shared__ float spr[2][NB];        // broadcast scaled pivot row (dbl buf)
    __shared__ float sipv[NB];
    const int l = blockIdx.y;
    int jt = blockIdx.x; jt += (jt >= kb);
    const int r = threadIdx.x;
    float* S = g_M[l];
    const int j0 = jt * NB;

    float t[NB], m[NB];
    #pragma unroll
    for (int c = 0; c < NB; c++) t[c] = S[r * U + j0 + c];
    #pragma unroll
    for (int c = 0; c < NB; c++) m[c] = g_Mul[l][r * NB + c];
    if (r < NB) sipv[r] = g_ipiv[l][kb * NB + r];
    __syncthreads();

    #pragma unroll
    for (int p = 0; p < NB; p++) {
        const int gp = kb * NB + p;
        if (r == gp) {
            const float ip = sipv[p];
            #pragma unroll
            for (int c = 0; c < NB; c++) { t[c] *= ip; spr[p & 1][c] = t[c]; }
        }
        __syncthreads();
        if (r != gp) {
            const float f = m[p];
            #pragma unroll
            for (int c = 0; c < NB; c++) t[c] -= f * spr[p & 1][c];
        }
        // next write targets the other buffer; the following step's
        // barrier orders reuse of this one.
        __syncthreads();
    }

    #pragma unroll
    for (int c = 0; c < NB; c++) S[r * U + j0 + c] = t[c];
}

// =====================================================================
// 2) full 256-K GEMM body (proven round-5 code) for Newton + chain
// =====================================================================
__device__ __forceinline__ void gemm64_body(const float* __restrict__ A,
                                            const float* __restrict__ Bm,
                                            float* __restrict__ C, int mode,
                                            int bx, int by) {
    __shared__ __align__(16) float As[32][68];
    __shared__ __align__(16) float Bs[32][68];
    const int tid = threadIdx.x;
    const int i0 = by * 64, j0 = bx * 64;
    const int rf = (tid >> 4) * 4, cf = (tid & 15) * 4;
    float acc[4][4];
    #pragma unroll
    for (int r = 0; r < 4; r++)
        #pragma unroll
        for (int c = 0; c < 4; c++) acc[r][c] = 0.0f;

    for (int k0 = 0; k0 < U; k0 += 32) {
        #pragma unroll
        for (int m = 0; m < 2; m++) {
            int s = tid + m * 256;
            int ii = s >> 3, kc = (s & 7) * 4;
            float4 a = *(const float4*)&A[(i0 + ii) * U + k0 + kc];
            As[kc + 0][ii] = a.x; As[kc + 1][ii] = a.y;
            As[kc + 2][ii] = a.z; As[kc + 3][ii] = a.w;
            int kk = s >> 4, jc = (s & 15) * 4;
            *(float4*)&Bs[kk][jc] = *(const float4*)&Bm[(k0 + kk) * U + j0 + jc];
        }
        __syncthreads();
        #pragma unroll
        for (int kk = 0; kk < 32; kk++) {
            float4 a4 = *(const float4*)&As[kk][rf];
            float4 b4 = *(const float4*)&Bs[kk][cf];
            float av[4] = {a4.x, a4.y, a4.z, a4.w};
            float bv[4] = {b4.x, b4.y, b4.z, b4.w};
            #pragma unroll
            for (int r = 0; r < 4; r++)
                #pragma unroll
                for (int c = 0; c < 4; c++) acc[r][c] += av[r] * bv[c];
        }
        __syncthreads();
    }
    #pragma unroll
    for (int r = 0; r < 4; r++) {
        int i = i0 + rf + r;
        #pragma unroll
        for (int c = 0; c < 4; c++) {
            int j = j0 + cf + c;
            float v = acc[r][c];
            if (mode) v = ((i == j) ? 2.0f : 0.0f) - v;
            C[i * U + j] = v;
        }
    }
}

__global__ __launch_bounds__(256) void newton64_kernel(const float* __restrict__ A,
                                                       const float* __restrict__ Bm,
                                                       float* __restrict__ C, int mode) {
    const int l = blockIdx.z;
    gemm64_body(A + (size_t)l * SZ, Bm + (size_t)l * SZ, C + (size_t)l * SZ,
                mode, blockIdx.x, blockIdx.y);
}

__global__ __launch_bounds__(256) void chain64_kernel(const float* __restrict__ MTnl,
                                                      const float* __restrict__ Ml,
                                                      const float* __restrict__ Xin,
                                                      const float* __restrict__ Yin,
                                                      float* __restrict__ Xout,
                                                      float* __restrict__ Yout) {
    if (blockIdx.z == 0) gemm64_body(MTnl, Yin, Xout, 0, blockIdx.x, blockIdx.y);
    else                 gemm64_body(Ml,   Xin, Yout, 0, blockIdx.x, blockIdx.y);
}

// =====================================================================
// 3) g_MTn = -(g_M)^T
// =====================================================================
__global__ void transneg_kernel() {
    const int l = blockIdx.z;
    __shared__ float t[32][33];
    const int x0 = blockIdx.x * 32, y0 = blockIdx.y * 32;
    const int tx = threadIdx.x, ty = threadIdx.y;
    #pragma unroll
    for (int i = 0; i < 32; i += 8)
        t[ty + i][tx] = g_M[l][(y0 + ty + i) * U + x0 + tx];
    __syncthreads();
    #pragma unroll
    for (int i = 0; i < 32; i += 8)
        g_MTn[l][(x0 + ty + i) * U + y0 + tx] = -t[tx][ty + i];
}

// =====================================================================
// 4) chain init: CX0 = MTn[0], CY0 = M[0]; zero const buffers
// =====================================================================
__global__ __launch_bounds__(256) void chain_init_kernel() {
    const int s = blockIdx.x * 256 + threadIdx.x;
    ((float4*)g_CX[0])[s] = ((const float4*)g_MTn[0])[s];
    ((float4*)g_CY[0])[s] = ((const float4*)g_M[0])[s];
    if (s < 256) ((float4*)g_c)[s] = make_float4(0.f, 0.f, 0.f, 0.f);
}

// =====================================================================
// 5) constant chain: c0' = MTn_l*c1 ; c1' = M_l*(c0+q_l)
// =====================================================================
__global__ __launch_bounds__(256) void constmv_kernel(const float* __restrict__ MTnl,
                                                      const float* __restrict__ Ml,
                                                      const float* __restrict__ cin,
                                                      float* __restrict__ cout,
                                                      const float* __restrict__ ql) {
    __shared__ float rs[U];
    const int n = threadIdx.x;
    const int b = blockIdx.x;
    rs[n] = b ? (cin[n] + ql[n]) : cin[U + n];
    __syncthreads();
    const float* A = b ? Ml : MTnl;
    float acc = 0.0f;
    #pragma unroll 8
    for (int m = 0; m < U; m++) acc += A[n * U + m] * rs[m];
    cout[b * U + n] = acc;
}

// =====================================================================
// 6) foldG / foldF / final (proven round-5 code)
// =====================================================================
__global__ __launch_bounds__(256) void foldG_kernel(const float* __restrict__ Wout,
                                                    const float* __restrict__ K,
                                                    const float* __restrict__ c0,
                                                    const float* __restrict__ bin,
                                                    const float* __restrict__ bout) {
    __shared__ float Ws[U * DOUT];
    __shared__ float Gs[DOUT][U];
    const int m = threadIdx.x;
    for (int e = m; e < U * DOUT; e += 256) Ws[e] = Wout[e];
    __syncthreads();
    float acc[DOUT];
    #pragma unroll
    for (int d = 0; d < DOUT; d++) acc[d] = 0.0f;
    for (int n = 0; n < U; n++) {
        const float xv = K[n * U + m];
        #pragma unroll
        for (int d = 0; d < DOUT; d++) acc[d] += Ws[n * DOUT + d] * xv;
    }
    #pragma unroll
    for (int d = 0; d < DOUT; d++) { g_G[d * U + m] = acc[d]; Gs[d][m] = acc[d]; }
    __syncthreads();
    if (m < DOUT) {
        float f = bout[m];
        for (int e = 0; e < U; e++) f += Gs[m][e] * bin[e];
        for (int n = 0; n < U; n++) f += Ws[n * DOUT + m] * c0[n];
        g_f[m] = f;
    }
}

__global__ __launch_bounds__(256) void foldF_kernel(const float* __restrict__ Win) {
    __shared__ float Gs[DOUT * U];
    const int tid = threadIdx.x;
    for (int e = tid; e < DOUT * U; e += 256) Gs[e] = g_G[e];
    __syncthreads();
    const int k = blockIdx.x * 256 + tid;
    if (k >= DIN) return;
    float acc[DOUT];
    #pragma unroll
    for (int d = 0; d < DOUT; d++) acc[d] = 0.0f;
    for (int m = 0; m < U; m++) {
        const float w = Win[(size_t)k * U + m];
        #pragma unroll
        for (int d = 0; d < DOUT; d++) acc[d] += Gs[d * U + m] * w;
    }
    #pragma unroll
    for (int d = 0; d < DOUT; d++) g_F[k * DOUT + d] = acc[d];
}

__global__ __launch_bounds__(128) void final_kernel(const float* __restrict__ x,
                                                    float* __restrict__ out) {
    __shared__ float Fs[DIN * DOUT];
    __shared__ float fsv[16];
    __shared__ __align__(16) float xs[4][16 * 33];
    const int tid = threadIdx.x;
    for (int e = tid; e < DIN * DOUT; e += 128) Fs[e] = g_F[e];
    if (tid < DOUT) fsv[tid] = g_f[tid];
    __syncthreads();

    const int w = tid >> 5, lane = tid & 31;
    const int row0 = blockIdx.x * 128 + w * 32;
    float* xw = xs[w];
    float acc[DOUT];
    #pragma unroll
    for (int d = 0; d < DOUT; d++) acc[d] = fsv[d];

    for (int k0 = 0; k0 < DIN; k0 += 16) {
        #pragma unroll
        for (int i = 0; i < 4; i++) {
            const int s = lane + 32 * i;
            const int r = s >> 2, kc = (s & 3) * 4;
            float4 v = *(const float4*)&x[(size_t)(row0 + r) * DIN + k0 + kc];
            xw[(kc + 0) * 33 + r] = v.x;
            xw[(kc + 1) * 33 + r] = v.y;
            xw[(kc + 2) * 33 + r] = v.z;
            xw[(kc + 3) * 33 + r] = v.w;
        }
        __syncwarp();
        #pragma unroll
        for (int kk = 0; kk < 16; kk++) {
            const float xv = xw[kk * 33 + lane];
            const float* Fp = &Fs[(k0 + kk) * DOUT];
            #pragma unroll
            for (int d = 0; d < DOUT; d++) acc[d] += xv * Fp[d];
        }
        __syncwarp();
    }
    const size_t j = (size_t)row0 + lane;
    #pragma unroll
    for (int d = 0; d < DOUT; d++) out[j * DOUT + d] = acc[d];
}

// =====================================================================
// launch
// =====================================================================
extern "C" void kernel_launch(void* const* d_in, const int* in_sizes, int n_in,
                              void* d_out, int out_size) {
    const float* x    = (const float*)d_in[0];
    const float* Win  = (const float*)d_in[1];
    const float* bin  = (const float*)d_in[2];
    const float* B0   = (const float*)d_in[3];
    const float* q    = (const float*)d_in[4];
    const float* Wout = (const float*)d_in[5];
    const float* bout = (const float*)d_in[6];
    float* out = (float*)d_out;

    float *pM, *pM2, *pR, *pMTn, *pCX, *pCY, *pc;
    cudaGetSymbolAddress((void**)&pM,   g_M);
    cudaGetSymbolAddress((void**)&pM2,  g_M2);
    cudaGetSymbolAddress((void**)&pR,   g_R);
    cudaGetSymbolAddress((void**)&pMTn, g_MTn);
    cudaGetSymbolAddress((void**)&pCX,  g_CX);
    cudaGetSymbolAddress((void**)&pCY,  g_CY);
    cudaGetSymbolAddress((void**)&pc,   g_c);

    // --- panel-blocked GENP-GJ inversion (exact monolithic arithmetic) ---
    copyM_kernel<<<NL * SZ / 1024, 256>>>(B0);
    for (int kb = 0; kb < U / NB; kb++) {
        panelA_kernel<<<NL, 256>>>(kb);
        panelB_kernel<<<dim3(U / NB - 1, NL), 256>>>(kb);
    }

    // --- 2 Newton-Schulz refinement steps (proven) ---
    dim3 ng(4, 4, NL);
    newton64_kernel<<<ng, 256>>>(B0, pM, pR, 1);    // R  = 2I - B0*M
    newton64_kernel<<<ng, 256>>>(pM, pR, pM2, 0);   // M2 = M*R
    newton64_kernel<<<ng, 256>>>(B0, pM2, pR, 1);   // R  = 2I - B0*M2
    newton64_kernel<<<ng, 256>>>(pM2, pR, pM, 0);   // M  = M2*R
    transneg_kernel<<<dim3(8, 8, NL), dim3(32, 8)>>>();

    // --- compose K = MTn6*M5*MTn4*M3*MTn2*M1 via X/Y chain ---
    chain_init_kernel<<<64, 256>>>();
    for (int l = 1; l < NL; l++) {
        const int cb = (l - 1) & 1, nb = l & 1;
        chain64_kernel<<<dim3(4, 4, 2), 256>>>(
            pMTn + (size_t)l * SZ, pM + (size_t)l * SZ,
            pCX + (size_t)cb * SZ, pCY + (size_t)cb * SZ,
            pCX + (size_t)nb * SZ, pCY + (size_t)nb * SZ);
    }
    // --- constant chain (6 steps); final c0 lands in buffer 0 ---
    for (int l = 0; l < NL; l++) {
        const int cb = l & 1, nb = (l + 1) & 1;
        constmv_kernel<<<2, 256>>>(pMTn + (size_t)l * SZ, pM + (size_t)l * SZ,
                                   pc + cb * 2 * U, pc + nb * 2 * U, q + l * U);
    }

    // --- fold everything into F (10x784) and f (10) ---
    foldG_kernel<<<1, 256>>>(Wout, pCX + SZ, pc, bin, bout);
    foldF_kernel<<<4, 256>>>(Win);

    // --- single memory-bound pass over x ---
    final_kernel<<<BATCH / 128, 128>>>(x, out);
}

// round 10
// speedup vs baseline: 11.5228x; 1.6548x over previous
#include <cuda_runtime.h>
#include <math.h>
#include <stdint.h>

#define U     256
#define SZ    65536          // U*U
#define BATCH 32768
#define NL    6
#define DIN   784
#define DOUT  10
#define NB    32             // panel width

// ===================== device-global scratch (no runtime allocs) =====================
__device__ float g_M   [NL][SZ];      // working matrix -> B0^-1
__device__ float g_M2  [NL][SZ];      // Newton temp
__device__ float g_R   [NL][SZ];      // Newton temp
__device__ float g_MTn [NL][SZ];
__device__ float g_Mul [NL][NB * U];  // multipliers, [p][r] (coalesced)
__device__ float g_ipiv[NL][U];       // 1/pivot per global step
__device__ float g_CX  [2][SZ];       // chain ping-pong
__device__ float g_CY  [2][SZ];
__device__ float g_c   [2][2 * U];    // constant chain [buf][c0|c1]
__device__ float g_G   [DOUT * U];
__device__ float g_F   [DIN * DOUT];
__device__ float g_f   [16];

// =====================================================================
// 0) g_M = B0  (fresh copy each replay)
// =====================================================================
__global__ __launch_bounds__(256) void copyM_kernel(const float* __restrict__ B0) {
    const size_t i = (size_t)blockIdx.x * 256 + threadIdx.x;
    ((float4*)g_M)[i] = ((const float4*)B0)[i];
}

// =====================================================================
// 1a) Panel factorization, REGISTER-RESIDENT, 1 barrier/step.
//     Thread r owns panel row r in registers (NB floats). Per step the
//     pivot thread scales its row and broadcasts via a ping-pong smem
//     buffer; everyone else subtracts f*sp from registers. Arithmetic
//     sequence is bit-identical to the proven round-9 panelA.
// =====================================================================
__global__ __launch_bounds__(256) void panelA_kernel(int kb) {
    __shared__ float spb[2][NB];
    const int l = blockIdx.x;
    const int r = threadIdx.x;          // row
    float* S = g_M[l];
    const int c0 = kb * NB;

    float t[NB];
    #pragma unroll
    for (int c = 0; c < NB; c += 4)
        *(float4*)&t[c] = *(const float4*)&S[r * U + c0 + c];

    #pragma unroll
    for (int p = 0; p < NB; p++) {
        const int gp = c0 + p;          // global pivot row
        if (r == gp) {
            g_Mul[l][p * U + r] = t[p];           // defined (unused for pivot)
            const float ip = 1.0f / t[p];
            g_ipiv[l][gp] = ip;
            #pragma unroll
            for (int c = 0; c < NB; c++) t[c] = (c == p) ? ip : t[c] * ip;
            #pragma unroll
            for (int c = 0; c < NB; c++) spb[p & 1][c] = t[c];
        }
        __syncthreads();
        if (r != gp) {
            const float f = t[p];                 // current col-p value = multiplier
            g_Mul[l][p * U + r] = f;              // coalesced store
            const float ip = spb[p & 1][p];       // = 1/pivot
            #pragma unroll
            for (int c = 0; c < NB; c++) t[c] -= f * spb[p & 1][c];
            t[p] = -f * ip;
        }
    }

    #pragma unroll
    for (int c = 0; c < NB; c += 4)
        *(float4*)&S[r * U + c0 + c] = *(float4*)&t[c];
}

// =====================================================================
// 1b) Outside-column update, REGISTER-RESIDENT, 1 barrier/step.
//     Replays the same NB rank-1 row ops using recorded multipliers.
//     grid (7 tiles, NL). Bit-identical arithmetic to round-9 panelB.
// =====================================================================
__global__ __launch_bounds__(256) void panelB_kernel(int kb) {
    __shared__ float spr[2][NB];
    __shared__ float sipv[NB];
    const int l = blockIdx.y;
    int jt = blockIdx.x; jt += (jt >= kb);
    const int r = threadIdx.x;
    float* S = g_M[l];
    const int j0 = jt * NB;

    float t[NB], m[NB];
    #pragma unroll
    for (int c = 0; c < NB; c += 4)
        *(float4*)&t[c] = *(const float4*)&S[r * U + j0 + c];
    #pragma unroll
    for (int p = 0; p < NB; p++) m[p] = g_Mul[l][p * U + r];   // coalesced
    if (r < NB) sipv[r] = g_ipiv[l][kb * NB + r];
    __syncthreads();

    #pragma unroll
    for (int p = 0; p < NB; p++) {
        const int gp = kb * NB + p;
        if (r == gp) {
            const float ip = sipv[p];
            #pragma unroll
            for (int c = 0; c < NB; c++) { t[c] *= ip; spr[p & 1][c] = t[c]; }
        }
        __syncthreads();
        if (r != gp) {
            const float f = m[p];
            #pragma unroll
            for (int c = 0; c < NB; c++) t[c] -= f * spr[p & 1][c];
        }
    }

    #pragma unroll
    for (int c = 0; c < NB; c += 4)
        *(float4*)&S[r * U + j0 + c] = *(float4*)&t[c];
}

// =====================================================================
// 2) full 256-K GEMM body (proven round-5 code) for Newton + chain
// =====================================================================
__device__ __forceinline__ void gemm64_body(const float* __restrict__ A,
                                            const float* __restrict__ Bm,
                                            float* __restrict__ C, int mode,
                                            int bx, int by) {
    __shared__ __align__(16) float As[32][68];
    __shared__ __align__(16) float Bs[32][68];
    const int tid = threadIdx.x;
    const int i0 = by * 64, j0 = bx * 64;
    const int rf = (tid >> 4) * 4, cf = (tid & 15) * 4;
    float acc[4][4];
    #pragma unroll
    for (int r = 0; r < 4; r++)
        #pragma unroll
        for (int c = 0; c < 4; c++) acc[r][c] = 0.0f;

    for (int k0 = 0; k0 < U; k0 += 32) {
        #pragma unroll
        for (int m = 0; m < 2; m++) {
            int s = tid + m * 256;
            int ii = s >> 3, kc = (s & 7) * 4;
            float4 a = *(const float4*)&A[(i0 + ii) * U + k0 + kc];
            As[kc + 0][ii] = a.x; As[kc + 1][ii] = a.y;
            As[kc + 2][ii] = a.z; As[kc + 3][ii] = a.w;
            int kk = s >> 4, jc = (s & 15) * 4;
            *(float4*)&Bs[kk][jc] = *(const float4*)&Bm[(k0 + kk) * U + j0 + jc];
        }
        __syncthreads();
        #pragma unroll
        for (int kk = 0; kk < 32; kk++) {
            float4 a4 = *(const float4*)&As[kk][rf];
            float4 b4 = *(const float4*)&Bs[kk][cf];
            float av[4] = {a4.x, a4.y, a4.z, a4.w};
            float bv[4] = {b4.x, b4.y, b4.z, b4.w};
            #pragma unroll
            for (int r = 0; r < 4; r++)
                #pragma unroll
                for (int c = 0; c < 4; c++) acc[r][c] += av[r] * bv[c];
        }
        __syncthreads();
    }
    #pragma unroll
    for (int r = 0; r < 4; r++) {
        int i = i0 + rf + r;
        #pragma unroll
        for (int c = 0; c < 4; c++) {
            int j = j0 + cf + c;
            float v = acc[r][c];
            if (mode) v = ((i == j) ? 2.0f : 0.0f) - v;
            C[i * U + j] = v;
        }
    }
}

__global__ __launch_bounds__(256) void newton64_kernel(const float* __restrict__ A,
                                                       const float* __restrict__ Bm,
                                                       float* __restrict__ C, int mode) {
    const int l = blockIdx.z;
    gemm64_body(A + (size_t)l * SZ, Bm + (size_t)l * SZ, C + (size_t)l * SZ,
                mode, blockIdx.x, blockIdx.y);
}

__global__ __launch_bounds__(256) void chain64_kernel(const float* __restrict__ MTnl,
                                                      const float* __restrict__ Ml,
                                                      const float* __restrict__ Xin,
                                                      const float* __restrict__ Yin,
                                                      float* __restrict__ Xout,
                                                      float* __restrict__ Yout) {
    if (blockIdx.z == 0) gemm64_body(MTnl, Yin, Xout, 0, blockIdx.x, blockIdx.y);
    else                 gemm64_body(Ml,   Xin, Yout, 0, blockIdx.x, blockIdx.y);
}

// =====================================================================
// 3) g_MTn = -(g_M)^T
// =====================================================================
__global__ void transneg_kernel() {
    const int l = blockIdx.z;
    __shared__ float t[32][33];
    const int x0 = blockIdx.x * 32, y0 = blockIdx.y * 32;
    const int tx = threadIdx.x, ty = threadIdx.y;
    #pragma unroll
    for (int i = 0; i < 32; i += 8)
        t[ty + i][tx] = g_M[l][(y0 + ty + i) * U + x0 + tx];
    __syncthreads();
    #pragma unroll
    for (int i = 0; i < 32; i += 8)
        g_MTn[l][(x0 + ty + i) * U + y0 + tx] = -t[tx][ty + i];
}

// =====================================================================
// 4) chain init: CX0 = MTn[0], CY0 = M[0]; zero const buffers
// =====================================================================
__global__ __launch_bounds__(256) void chain_init_kernel() {
    const int s = blockIdx.x * 256 + threadIdx.x;
    ((float4*)g_CX[0])[s] = ((const float4*)g_MTn[0])[s];
    ((float4*)g_CY[0])[s] = ((const float4*)g_M[0])[s];
    if (s < 256) ((float4*)g_c)[s] = make_float4(0.f, 0.f, 0.f, 0.f);
}

// =====================================================================
// 5) constant chain: c0' = MTn_l*c1 ; c1' = M_l*(c0+q_l)
// =====================================================================
__global__ __launch_bounds__(256) void constmv_kernel(const float* __restrict__ MTnl,
                                                      const float* __restrict__ Ml,
                                                      const float* __restrict__ cin,
                                                      float* __restrict__ cout,
                                                      const float* __restrict__ ql) {
    __shared__ float rs[U];
    const int n = threadIdx.x;
    const int b = blockIdx.x;
    rs[n] = b ? (cin[n] + ql[n]) : cin[U + n];
    __syncthreads();
    const float* A = b ? Ml : MTnl;
    float acc = 0.0f;
    #pragma unroll 8
    for (int m = 0; m < U; m++) acc += A[n * U + m] * rs[m];
    cout[b * U + n] = acc;
}

// =====================================================================
// 6) foldG / foldF / final (proven round-5 code)
// =====================================================================
__global__ __launch_bounds__(256) void foldG_kernel(const float* __restrict__ Wout,
                                                    const float* __restrict__ K,
                                                    const float* __restrict__ c0,
                                                    const float* __restrict__ bin,
                                                    const float* __restrict__ bout) {
    __shared__ float Ws[U * DOUT];
    __shared__ float Gs[DOUT][U];
    const int m = threadIdx.x;
    for (int e = m; e < U * DOUT; e += 256) Ws[e] = Wout[e];
    __syncthreads();
    float acc[DOUT];
    #pragma unroll
    for (int d = 0; d < DOUT; d++) acc[d] = 0.0f;
    for (int n = 0; n < U; n++) {
        const float xv = K[n * U + m];
        #pragma unroll
        for (int d = 0; d < DOUT; d++) acc[d] += Ws[n * DOUT + d] * xv;
    }
    #pragma unroll
    for (int d = 0; d < DOUT; d++) { g_G[d * U + m] = acc[d]; Gs[d][m] = acc[d]; }
    __syncthreads();
    if (m < DOUT) {
        float f = bout[m];
        for (int e = 0; e < U; e++) f += Gs[m][e] * bin[e];
        for (int n = 0; n < U; n++) f += Ws[n * DOUT + m] * c0[n];
        g_f[m] = f;
    }
}

__global__ __launch_bounds__(256) void foldF_kernel(const float* __restrict__ Win) {
    __shared__ float Gs[DOUT * U];
    const int tid = threadIdx.x;
    for (int e = tid; e < DOUT * U; e += 256) Gs[e] = g_G[e];
    __syncthreads();
    const int k = blockIdx.x * 256 + tid;
    if (k >= DIN) return;
    float acc[DOUT];
    #pragma unroll
    for (int d = 0; d < DOUT; d++) acc[d] = 0.0f;
    for (int m = 0; m < U; m++) {
        const float w = Win[(size_t)k * U + m];
        #pragma unroll
        for (int d = 0; d < DOUT; d++) acc[d] += Gs[d * U + m] * w;
    }
    #pragma unroll
    for (int d = 0; d < DOUT; d++) g_F[k * DOUT + d] = acc[d];
}

__global__ __launch_bounds__(128) void final_kernel(const float* __restrict__ x,
                                                    float* __restrict__ out) {
    __shared__ float Fs[DIN * DOUT];
    __shared__ float fsv[16];
    __shared__ __align__(16) float xs[4][16 * 33];
    const int tid = threadIdx.x;
    for (int e = tid; e < DIN * DOUT; e += 128) Fs[e] = g_F[e];
    if (tid < DOUT) fsv[tid] = g_f[tid];
    __syncthreads();

    const int w = tid >> 5, lane = tid & 31;
    const int row0 = blockIdx.x * 128 + w * 32;
    float* xw = xs[w];
    float acc[DOUT];
    #pragma unroll
    for (int d = 0; d < DOUT; d++) acc[d] = fsv[d];

    for (int k0 = 0; k0 < DIN; k0 += 16) {
        #pragma unroll
        for (int i = 0; i < 4; i++) {
            const int s = lane + 32 * i;
            const int r = s >> 2, kc = (s & 3) * 4;
            float4 v = *(const float4*)&x[(size_t)(row0 + r) * DIN + k0 + kc];
            xw[(kc + 0) * 33 + r] = v.x;
            xw[(kc + 1) * 33 + r] = v.y;
            xw[(kc + 2) * 33 + r] = v.z;
            xw[(kc + 3) * 33 + r] = v.w;
        }
        __syncwarp();
        #pragma unroll
        for (int kk = 0; kk < 16; kk++) {
            const float xv = xw[kk * 33 + lane];
            const float* Fp = &Fs[(k0 + kk) * DOUT];
            #pragma unroll
            for (int d = 0; d < DOUT; d++) acc[d] += xv * Fp[d];
        }
        __syncwarp();
    }
    const size_t j = (size_t)row0 + lane;
    #pragma unroll
    for (int d = 0; d < DOUT; d++) out[j * DOUT + d] = acc[d];
}

// =====================================================================
// launch
// =====================================================================
extern "C" void kernel_launch(void* const* d_in, const int* in_sizes, int n_in,
                              void* d_out, int out_size) {
    const float* x    = (const float*)d_in[0];
    const float* Win  = (const float*)d_in[1];
    const float* bin  = (const float*)d_in[2];
    const float* B0   = (const float*)d_in[3];
    const float* q    = (const float*)d_in[4];
    const float* Wout = (const float*)d_in[5];
    const float* bout = (const float*)d_in[6];
    float* out = (float*)d_out;

    float *pM, *pM2, *pR, *pMTn, *pCX, *pCY, *pc;
    cudaGetSymbolAddress((void**)&pM,   g_M);
    cudaGetSymbolAddress((void**)&pM2,  g_M2);
    cudaGetSymbolAddress((void**)&pR,   g_R);
    cudaGetSymbolAddress((void**)&pMTn, g_MTn);
    cudaGetSymbolAddress((void**)&pCX,  g_CX);
    cudaGetSymbolAddress((void**)&pCY,  g_CY);
    cudaGetSymbolAddress((void**)&pc,   g_c);

    // --- panel-blocked GENP-GJ inversion (exact monolithic arithmetic) ---
    copyM_kernel<<<NL * SZ / 1024, 256>>>(B0);
    for (int kb = 0; kb < U / NB; kb++) {
        panelA_kernel<<<NL, 256>>>(kb);
        panelB_kernel<<<dim3(U / NB - 1, NL), 256>>>(kb);
    }

    // --- 2 Newton-Schulz refinement steps (proven) ---
    dim3 ng(4, 4, NL);
    newton64_kernel<<<ng, 256>>>(B0, pM, pR, 1);    // R  = 2I - B0*M
    newton64_kernel<<<ng, 256>>>(pM, pR, pM2, 0);   // M2 = M*R
    newton64_kernel<<<ng, 256>>>(B0, pM2, pR, 1);   // R  = 2I - B0*M2
    newton64_kernel<<<ng, 256>>>(pM2, pR, pM, 0);   // M  = M2*R
    transneg_kernel<<<dim3(8, 8, NL), dim3(32, 8)>>>();

    // --- compose K = MTn6*M5*MTn4*M3*MTn2*M1 via X/Y chain ---
    chain_init_kernel<<<64, 256>>>();
    for (int l = 1; l < NL; l++) {
        const int cb = (l - 1) & 1, nb = l & 1;
        chain64_kernel<<<dim3(4, 4, 2), 256>>>(
            pMTn + (size_t)l * SZ, pM + (size_t)l * SZ,
            pCX + (size_t)cb * SZ, pCY + (size_t)cb * SZ,
            pCX + (size_t)nb * SZ, pCY + (size_t)nb * SZ);
    }
    // --- constant chain (6 steps); final c0 lands in buffer 0 ---
    for (int l = 0; l < NL; l++) {
        const int cb = l & 1, nb = (l + 1) & 1;
        constmv_kernel<<<2, 256>>>(pMTn + (size_t)l * SZ, pM + (size_t)l * SZ,
                                   pc + cb * 2 * U, pc + nb * 2 * U, q + l * U);
    }

    // --- fold everything into F (10x784) and f (10) ---
    foldG_kernel<<<1, 256>>>(Wout, pCX + SZ, pc, bin, bout);
    foldF_kernel<<<4, 256>>>(Win);

    // --- single memory-bound pass over x ---
    final_kernel<<<BATCH / 128, 128>>>(x, out);
}

// round 11
// speedup vs baseline: 12.9535x; 1.1242x over previous
#include <cuda_runtime.h>
#include <math.h>
#include <stdint.h>

#define U     256
#define SZ    65536          // U*U
#define BATCH 32768
#define NL    6
#define DIN   784
#define DOUT  10
#define NB    32             // panel width

// ===================== device-global scratch (no runtime allocs) =====================
__device__ float g_M   [NL][SZ];      // GENP working matrix; later reused as tree bufs
__device__ float g_M2  [NL][SZ];      // Newton-refined inverse
__device__ float g_R   [NL][SZ];      // Newton residual
__device__ float g_MTn [NL][SZ];
__device__ float g_Mul [2][NL][NB * U]; // multipliers, double-buffered, [p][r] coalesced
__device__ float g_ipiv[NL][U];       // 1/pivot per global step
__device__ float g_c   [2][2 * U];    // constant chain [buf][c0|c1]
__device__ float g_G   [DOUT * U];
__device__ float g_F   [DIN * DOUT];
__device__ float g_f   [16];

// =====================================================================
// 0) g_M = B0 fresh copy each replay; also zero const-chain buffers
// =====================================================================
__global__ __launch_bounds__(256) void copyM_kernel(const float* __restrict__ B0) {
    const size_t i = (size_t)blockIdx.x * 256 + threadIdx.x;
    ((float4*)g_M)[i] = ((const float4*)B0)[i];
    if (blockIdx.x == 0)
        ((float4*)g_c)[threadIdx.x] = make_float4(0.f, 0.f, 0.f, 0.f);
}

// =====================================================================
// 1a) Panel factorization for block 0 (register-resident, proven r10 code).
//     Writes multipliers to g_Mul[0].
// =====================================================================
__global__ __launch_bounds__(256) void panelA_kernel() {
    __shared__ __align__(16) float spb[2][NB];
    const int l = blockIdx.x;
    const int r = threadIdx.x;
    float* S = g_M[l];

    float t[NB];
    #pragma unroll
    for (int c = 0; c < NB; c += 4)
        *(float4*)&t[c] = *(const float4*)&S[r * U + c];

    #pragma unroll
    for (int p = 0; p < NB; p++) {
        const int gp = p;               // block 0: global pivot row = p
        if (r == gp) {
            g_Mul[0][l][p * U + r] = t[p];
            const float ip = 1.0f / t[p];
            g_ipiv[l][gp] = ip;
            #pragma unroll
            for (int c = 0; c < NB; c++) t[c] = (c == p) ? ip : t[c] * ip;
            #pragma unroll
            for (int c = 0; c < NB; c++) spb[p & 1][c] = t[c];
        }
        __syncthreads();
        if (r != gp) {
            const float f = t[p];
            g_Mul[0][l][p * U + r] = f;
            const float ip = spb[p & 1][p];
            #pragma unroll
            for (int c = 0; c < NB; c += 4) {
                float4 s4 = *(const float4*)&spb[p & 1][c];
                t[c + 0] -= f * s4.x; t[c + 1] -= f * s4.y;
                t[c + 2] -= f * s4.z; t[c + 3] -= f * s4.w;
            }
            t[p] = -f * ip;
        }
    }

    #pragma unroll
    for (int c = 0; c < NB; c += 4)
        *(float4*)&S[r * U + c] = *(float4*)&t[c];
}

// =====================================================================
// 1b) FUSED: panelB replay for step kb on tiles != kb; the CTA owning
//     tile kb+1 continues with panelA(kb+1) on its register tile.
//     Mul double-buffer: read kb&1, write (kb+1)&1.
// =====================================================================
__global__ __launch_bounds__(256) void fusedBA_kernel(int kb) {
    __shared__ __align__(16) float spr[2][NB];
    __shared__ float sipv[NB];
    const int l = blockIdx.y;
    int jt = blockIdx.x; jt += (jt >= kb);
    const int r = threadIdx.x;
    float* S = g_M[l];
    const int j0 = jt * NB;
    const int mb = kb & 1;

    float t[NB], m[NB];
    #pragma unroll
    for (int c = 0; c < NB; c += 4)
        *(float4*)&t[c] = *(const float4*)&S[r * U + j0 + c];
    #pragma unroll
    for (int p = 0; p < NB; p++) m[p] = g_Mul[mb][l][p * U + r];
    if (r < NB) sipv[r] = g_ipiv[l][kb * NB + r];
    __syncthreads();

    #pragma unroll
    for (int p = 0; p < NB; p++) {
        const int gp = kb * NB + p;
        if (r == gp) {
            const float ip = sipv[p];
            #pragma unroll
            for (int c = 0; c < NB; c++) { t[c] *= ip; spr[p & 1][c] = t[c]; }
        }
        __syncthreads();
        if (r != gp) {
            const float f = m[p];
            #pragma unroll
            for (int c = 0; c < NB; c += 4) {
                float4 s4 = *(const float4*)&spr[p & 1][c];
                t[c + 0] -= f * s4.x; t[c + 1] -= f * s4.y;
                t[c + 2] -= f * s4.z; t[c + 3] -= f * s4.w;
            }
        }
    }

    if (jt != kb + 1) {
        #pragma unroll
        for (int c = 0; c < NB; c += 4)
            *(float4*)&S[r * U + j0 + c] = *(float4*)&t[c];
        return;
    }

    // ---- panelA for block kb+1 on the register-resident tile ----
    // spr epochs: panelA step0 writes buf0 (replay ended on buf1, no race);
    // each subsequent write is ordered by the intervening barrier.
    const int c0 = (kb + 1) * NB;
    const int wb = (kb + 1) & 1;
    #pragma unroll
    for (int p = 0; p < NB; p++) {
        const int gp = c0 + p;
        if (r == gp) {
            g_Mul[wb][l][p * U + r] = t[p];
            const float ip = 1.0f / t[p];
            g_ipiv[l][gp] = ip;
            #pragma unroll
            for (int c = 0; c < NB; c++) t[c] = (c == p) ? ip : t[c] * ip;
            #pragma unroll
            for (int c = 0; c < NB; c++) spr[p & 1][c] = t[c];
        }
        __syncthreads();
        if (r != gp) {
            const float f = t[p];
            g_Mul[wb][l][p * U + r] = f;
            const float ip = spr[p & 1][p];
            #pragma unroll
            for (int c = 0; c < NB; c += 4) {
                float4 s4 = *(const float4*)&spr[p & 1][c];
                t[c + 0] -= f * s4.x; t[c + 1] -= f * s4.y;
                t[c + 2] -= f * s4.z; t[c + 3] -= f * s4.w;
            }
            t[p] = -f * ip;
        }
    }
    #pragma unroll
    for (int c = 0; c < NB; c += 4)
        *(float4*)&S[r * U + c0 + c] = *(float4*)&t[c];
}

// =====================================================================
// 1c) Trailing panelB for the last block step (kb = 7), Mul buffer 1.
// =====================================================================
__global__ __launch_bounds__(256) void panelB_kernel(int kb) {
    __shared__ __align__(16) float spr[2][NB];
    __shared__ float sipv[NB];
    const int l = blockIdx.y;
    int jt = blockIdx.x; jt += (jt >= kb);
    const int r = threadIdx.x;
    float* S = g_M[l];
    const int j0 = jt * NB;
    const int mb = kb & 1;

    float t[NB], m[NB];
    #pragma unroll
    for (int c = 0; c < NB; c += 4)
        *(float4*)&t[c] = *(const float4*)&S[r * U + j0 + c];
    #pragma unroll
    for (int p = 0; p < NB; p++) m[p] = g_Mul[mb][l][p * U + r];
    if (r < NB) sipv[r] = g_ipiv[l][kb * NB + r];
    __syncthreads();

    #pragma unroll
    for (int p = 0; p < NB; p++) {
        const int gp = kb * NB + p;
        if (r == gp) {
            const float ip = sipv[p];
            #pragma unroll
            for (int c = 0; c < NB; c++) { t[c] *= ip; spr[p & 1][c] = t[c]; }
        }
        __syncthreads();
        if (r != gp) {
            const float f = m[p];
            #pragma unroll
            for (int c = 0; c < NB; c += 4) {
                float4 s4 = *(const float4*)&spr[p & 1][c];
                t[c + 0] -= f * s4.x; t[c + 1] -= f * s4.y;
                t[c + 2] -= f * s4.z; t[c + 3] -= f * s4.w;
            }
        }
    }

    #pragma unroll
    for (int c = 0; c < NB; c += 4)
        *(float4*)&S[r * U + j0 + c] = *(float4*)&t[c];
}

// =====================================================================
// 2) full 256-K GEMM body (proven round-5 code)
// =====================================================================
__device__ __forceinline__ void gemm64_body(const float* __restrict__ A,
                                            const float* __restrict__ Bm,
                                            float* __restrict__ C, int mode,
                                            int bx, int by) {
    __shared__ __align__(16) float As[32][68];
    __shared__ __align__(16) float Bs[32][68];
    const int tid = threadIdx.x;
    const int i0 = by * 64, j0 = bx * 64;
    const int rf = (tid >> 4) * 4, cf = (tid & 15) * 4;
    float acc[4][4];
    #pragma unroll
    for (int r = 0; r < 4; r++)
        #pragma unroll
        for (int c = 0; c < 4; c++) acc[r][c] = 0.0f;

    for (int k0 = 0; k0 < U; k0 += 32) {
        #pragma unroll
        for (int m = 0; m < 2; m++) {
            int s = tid + m * 256;
            int ii = s >> 3, kc = (s & 7) * 4;
            float4 a = *(const float4*)&A[(i0 + ii) * U + k0 + kc];
            As[kc + 0][ii] = a.x; As[kc + 1][ii] = a.y;
            As[kc + 2][ii] = a.z; As[kc + 3][ii] = a.w;
            int kk = s >> 4, jc = (s & 15) * 4;
            *(float4*)&Bs[kk][jc] = *(const float4*)&Bm[(k0 + kk) * U + j0 + jc];
        }
        __syncthreads();
        #pragma unroll
        for (int kk = 0; kk < 32; kk++) {
            float4 a4 = *(const float4*)&As[kk][rf];
            float4 b4 = *(const float4*)&Bs[kk][cf];
            float av[4] = {a4.x, a4.y, a4.z, a4.w};
            float bv[4] = {b4.x, b4.y, b4.z, b4.w};
            #pragma unroll
            for (int r = 0; r < 4; r++)
                #pragma unroll
                for (int c = 0; c < 4; c++) acc[r][c] += av[r] * bv[c];
        }
        __syncthreads();
    }
    #pragma unroll
    for (int r = 0; r < 4; r++) {
        int i = i0 + rf + r;
        #pragma unroll
        for (int c = 0; c < 4; c++) {
            int j = j0 + cf + c;
            float v = acc[r][c];
            if (mode) v = ((i == j) ? 2.0f : 0.0f) - v;
            C[i * U + j] = v;
        }
    }
}

__global__ __launch_bounds__(256) void newton64_kernel(const float* __restrict__ A,
                                                       const float* __restrict__ Bm,
                                                       float* __restrict__ C, int mode) {
    const int l = blockIdx.z;
    gemm64_body(A + (size_t)l * SZ, Bm + (size_t)l * SZ, C + (size_t)l * SZ,
                mode, blockIdx.x, blockIdx.y);
}

// generic z-strided product for the chain tree (strides in SZ units)
__global__ __launch_bounds__(256) void gemmz_kernel(const float* __restrict__ A, int sA,
                                                    const float* __restrict__ Bm, int sB,
                                                    float* __restrict__ C, int sC) {
    const int z = blockIdx.z;
    gemm64_body(A + (size_t)z * sA * SZ, Bm + (size_t)z * sB * SZ,
                C + (size_t)z * sC * SZ, 0, blockIdx.x, blockIdx.y);
}

// =====================================================================
// 3) g_MTn = -(g_M2)^T   (refined inverse)
// =====================================================================
__global__ void transneg_kernel() {
    const int l = blockIdx.z;
    __shared__ float t[32][33];
    const int x0 = blockIdx.x * 32, y0 = blockIdx.y * 32;
    const int tx = threadIdx.x, ty = threadIdx.y;
    #pragma unroll
    for (int i = 0; i < 32; i += 8)
        t[ty + i][tx] = g_M2[l][(y0 + ty + i) * U + x0 + tx];
    __syncthreads();
    #pragma unroll
    for (int i = 0; i < 32; i += 8)
        g_MTn[l][(x0 + ty + i) * U + y0 + tx] = -t[tx][ty + i];
}

// =====================================================================
// 4) constant chain: c0' = MTn_l*c1 ; c1' = M_l*(c0+q_l)
// =====================================================================
__global__ __launch_bounds__(256) void constmv_kernel(const float* __restrict__ MTnl,
                                                      const float* __restrict__ Ml,
                                                      const float* __restrict__ cin,
                                                      float* __restrict__ cout,
                                                      const float* __restrict__ ql) {
    __shared__ float rs[U];
    const int n = threadIdx.x;
    const int b = blockIdx.x;
    rs[n] = b ? (cin[n] + ql[n]) : cin[U + n];
    __syncthreads();
    const float* A = b ? Ml : MTnl;
    float acc = 0.0f;
    #pragma unroll 8
    for (int m = 0; m < U; m++) acc += A[n * U + m] * rs[m];
    cout[b * U + n] = acc;
}

// =====================================================================
// 5) foldG / foldF / final (proven round-5 code)
// =====================================================================
__global__ __launch_bounds__(256) void foldG_kernel(const float* __restrict__ Wout,
                                                    const float* __restrict__ K,
                                                    const float* __restrict__ c0,
                                                    const float* __restrict__ bin,
                                                    const float* __restrict__ bout) {
    __shared__ float Ws[U * DOUT];
    __shared__ float Gs[DOUT][U];
    const int m = threadIdx.x;
    for (int e = m; e < U * DOUT; e += 256) Ws[e] = Wout[e];
    __syncthreads();
    float acc[DOUT];
    #pragma unroll
    for (int d = 0; d < DOUT; d++) acc[d] = 0.0f;
    for (int n = 0; n < U; n++) {
        const float xv = K[n * U + m];
        #pragma unroll
        for (int d = 0; d < DOUT; d++) acc[d] += Ws[n * DOUT + d] * xv;
    }
    #pragma unroll
    for (int d = 0; d < DOUT; d++) { g_G[d * U + m] = acc[d]; Gs[d][m] = acc[d]; }
    __syncthreads();
    if (m < DOUT) {
        float f = bout[m];
        for (int e = 0; e < U; e++) f += Gs[m][e] * bin[e];
        for (int n = 0; n < U; n++) f += Ws[n * DOUT + m] * c0[n];
        g_f[m] = f;
    }
}

__global__ __launch_bounds__(256) void foldF_kernel(const float* __restrict__ Win) {
    __shared__ float Gs[DOUT * U];
    const int tid = threadIdx.x;
    for (int e = tid; e < DOUT * U; e += 256) Gs[e] = g_G[e];
    __syncthreads();
    const int k = blockIdx.x * 256 + tid;
    if (k >= DIN) return;
    float acc[DOUT];
    #pragma unroll
    for (int d = 0; d < DOUT; d++) acc[d] = 0.0f;
    for (int m = 0; m < U; m++) {
        const float w = Win[(size_t)k * U + m];
        #pragma unroll
        for (int d = 0; d < DOUT; d++) acc[d] += Gs[d * U + m] * w;
    }
    #pragma unroll
    for (int d = 0; d < DOUT; d++) g_F[k * DOUT + d] = acc[d];
}

__global__ __launch_bounds__(128) void final_kernel(const float* __restrict__ x,
                                                    float* __restrict__ out) {
    __shared__ float Fs[DIN * DOUT];
    __shared__ float fsv[16];
    __shared__ __align__(16) float xs[4][16 * 33];
    const int tid = threadIdx.x;
    for (int e = tid; e < DIN * DOUT; e += 128) Fs[e] = g_F[e];
    if (tid < DOUT) fsv[tid] = g_f[tid];
    __syncthreads();

    const int w = tid >> 5, lane = tid & 31;
    const int row0 = blockIdx.x * 128 + w * 32;
    float* xw = xs[w];
    float acc[DOUT];
    #pragma unroll
    for (int d = 0; d < DOUT; d++) acc[d] = fsv[d];

    for (int k0 = 0; k0 < DIN; k0 += 16) {
        #pragma unroll
        for (int i = 0; i < 4; i++) {
            const int s = lane + 32 * i;
            const int r = s >> 2, kc = (s & 3) * 4;
            float4 v = *(const float4*)&x[(size_t)(row0 + r) * DIN + k0 + kc];
            xw[(kc + 0) * 33 + r] = v.x;
            xw[(kc + 1) * 33 + r] = v.y;
            xw[(kc + 2) * 33 + r] = v.z;
            xw[(kc + 3) * 33 + r] = v.w;
        }
        __syncwarp();
        #pragma unroll
        for (int kk = 0; kk < 16; kk++) {
            const float xv = xw[kk * 33 + lane];
            const float* Fp = &Fs[(k0 + kk) * DOUT];
            #pragma unroll
            for (int d = 0; d < DOUT; d++) acc[d] += xv * Fp[d];
        }
        __syncwarp();
    }
    const size_t j = (size_t)row0 + lane;
    #pragma unroll
    for (int d = 0; d < DOUT; d++) out[j * DOUT + d] = acc[d];
}

// =====================================================================
// launch
// =====================================================================
extern "C" void kernel_launch(void* const* d_in, const int* in_sizes, int n_in,
                              void* d_out, int out_size) {
    const float* x    = (const float*)d_in[0];
    const float* Win  = (const float*)d_in[1];
    const float* bin  = (const float*)d_in[2];
    const float* B0   = (const float*)d_in[3];
    const float* q    = (const float*)d_in[4];
    const float* Wout = (const float*)d_in[5];
    const float* bout = (const float*)d_in[6];
    float* out = (float*)d_out;

    float *pM, *pM2, *pR, *pMTn, *pc;
    cudaGetSymbolAddress((void**)&pM,   g_M);
    cudaGetSymbolAddress((void**)&pM2,  g_M2);
    cudaGetSymbolAddress((void**)&pR,   g_R);
    cudaGetSymbolAddress((void**)&pMTn, g_MTn);
    cudaGetSymbolAddress((void**)&pc,   g_c);

    // --- GENP-GJ inversion, fused panel pipeline: 9 launches ---
    copyM_kernel<<<NL * SZ / 1024, 256>>>(B0);
    panelA_kernel<<<NL, 256>>>();
    for (int kb = 0; kb < U / NB - 1; kb++)
        fusedBA_kernel<<<dim3(U / NB - 1, NL), 256>>>(kb);
    panelB_kernel<<<dim3(U / NB - 1, NL), 256>>>(U / NB - 1);

    // --- 1 Newton-Schulz refinement step -> refined inverse in g_M2 ---
    dim3 ng(4, 4, NL);
    newton64_kernel<<<ng, 256>>>(B0, pM, pR, 1);    // R  = 2I - B0*M
    newton64_kernel<<<ng, 256>>>(pM, pR, pM2, 0);   // M2 = M*R
    transneg_kernel<<<dim3(8, 8, NL), dim3(32, 8)>>>();

    // --- chain tree: K = T2*(T1*T0), T_z = MTn[2z+1]*M2[2z]  (g_M reused) ---
    gemmz_kernel<<<dim3(4, 4, 3), 256>>>(pMTn + SZ, 2, pM2, 2, pM, 1);
    gemmz_kernel<<<dim3(4, 4, 1), 256>>>(pM + SZ, 0, pM, 0, pM + 3 * (size_t)SZ, 0);
    gemmz_kernel<<<dim3(4, 4, 1), 256>>>(pM + 2 * (size_t)SZ, 0, pM + 3 * (size_t)SZ, 0,
                                         pM + 4 * (size_t)SZ, 0);

    // --- constant chain (6 steps); final c0 lands in buffer 0 ---
    for (int l = 0; l < NL; l++) {
        const int cb = l & 1, nb = (l + 1) & 1;
        constmv_kernel<<<2, 256>>>(pMTn + (size_t)l * SZ, pM2 + (size_t)l * SZ,
                                   pc + cb * 2 * U, pc + nb * 2 * U, q + l * U);
    }

    // --- fold everything into F (10x784) and f (10) ---
    foldG_kernel<<<1, 256>>>(Wout, pM + 4 * (size_t)SZ, pc, bin, bout);
    foldF_kernel<<<4, 256>>>(Win);

    // --- single memory-bound pass over x ---
    final_kernel<<<BATCH / 128, 128>>>(x, out);
}

// round 12
// speedup vs baseline: 16.4667x; 1.2712x over previous
#include <cuda_runtime.h>
#include <math.h>
#include <stdint.h>

#define U     256
#define SZ    65536          // U*U
#define BATCH 32768
#define NL    6
#define DIN   784
#define DOUT  10
#define NB    32             // panel width
#define NSTEP (U / NB)       // 8 block steps

// ===================== device-global scratch (no runtime allocs) =====================
__device__ float g_M   [NL][SZ];          // GENP inverse; later reused as tree bufs
__device__ float g_M2  [NL][SZ];          // Newton-refined inverse
__device__ float g_R   [NL][SZ];          // Newton residual
__device__ float g_MTn [NL][SZ];          // -(M2)^T
__device__ float g_Mul8[NSTEP][NL][NB * U]; // multipliers, per-step buffers, [p][r]
__device__ float g_ipiv[NL][U];           // 1/pivot per global step
__device__ unsigned int g_flagw[NL][NSTEP];
__device__ float g_c   [2 * U];           // final constant (c0 in [0,U))
__device__ float g_G   [DOUT * U];
__device__ float g_F   [DIN * DOUT];
__device__ float g_f   [16];

// =====================================================================
// 0) zero the step flags (every replay)
// =====================================================================
__global__ __launch_bounds__(64) void initflags_kernel() {
    const int i = threadIdx.x;
    if (i < NL * NSTEP) ((unsigned int*)g_flagw)[i] = 0u;
}

// =====================================================================
// 1) PERSISTENT GENP-GJ inversion, one launch, flag-synced.
//    grid (8 tiles, NL layers), 256 threads; tile lives in registers.
//    Arithmetic sequence identical to the proven round-10 panel kernels;
//    pivot-scale for step p+1 is pipelined into phase p (same ops).
// =====================================================================
__global__ __launch_bounds__(256) void invert_kernel(const float* __restrict__ B0) {
    __shared__ __align__(16) float sp[2][NB];
    __shared__ float sipv[NB];
    const int l  = blockIdx.y;
    const int jt = blockIdx.x;
    const int r  = threadIdx.x;
    const float* A = B0 + (size_t)l * SZ;
    const int j0 = jt * NB;

    float t[NB];
    #pragma unroll
    for (int c = 0; c < NB; c += 4)
        *(float4*)&t[c] = *(const float4*)&A[r * U + j0 + c];

    #pragma unroll 1
    for (int kb = 0; kb < NSTEP; kb++) {
        float* Mul = &g_Mul8[kb][l][0];
        const int c0g = kb * NB;
        if (jt == kb) {
            // ---- panel factorization (pipelined pivot) ----
            if (r == c0g) {                       // pivot of step 0
                Mul[0 * U + r] = t[0];
                const float ip = 1.0f / t[0];
                g_ipiv[l][c0g] = ip;
                #pragma unroll
                for (int c = 0; c < NB; c++) t[c] = (c == 0) ? ip : t[c] * ip;
                #pragma unroll
                for (int c = 0; c < NB; c++) sp[0][c] = t[c];
            }
            #pragma unroll
            for (int p = 0; p < NB; p++) {
                __syncthreads();
                const int gp = c0g + p;
                if (r != gp) {
                    const float f = t[p];
                    Mul[p * U + r] = f;
                    const float ip = sp[p & 1][p];
                    #pragma unroll
                    for (int c = 0; c < NB; c += 4) {
                        float4 s4 = *(const float4*)&sp[p & 1][c];
                        t[c + 0] -= f * s4.x; t[c + 1] -= f * s4.y;
                        t[c + 2] -= f * s4.z; t[c + 3] -= f * s4.w;
                    }
                    t[p] = -f * ip;
                    if (p + 1 < NB && r == gp + 1) {
                        // pivot work for next step, same values as original
                        Mul[(p + 1) * U + r] = t[p + 1];
                        const float ip2 = 1.0f / t[p + 1];
                        g_ipiv[l][gp + 1] = ip2;
                        #pragma unroll
                        for (int c = 0; c < NB; c++)
                            t[c] = (c == p + 1) ? ip2 : t[c] * ip2;
                        #pragma unroll
                        for (int c = 0; c < NB; c++) sp[(p + 1) & 1][c] = t[c];
                    }
                }
            }
            __threadfence();
            __syncthreads();
            if (r == 0) atomicExch(&g_flagw[l][kb], 1u);
        } else {
            // ---- wait for panel kb, then replay its 32 rank-1 ops ----
            if (r == 0) {
                while (atomicAdd(&g_flagw[l][kb], 0u) == 0u) { }
            }
            __syncthreads();
            float m[NB];
            #pragma unroll
            for (int p = 0; p < NB; p++) m[p] = Mul[p * U + r];
            if (r < NB) sipv[r] = g_ipiv[l][c0g + r];
            __syncthreads();
            if (r == c0g) {                       // pivot of step 0
                const float ip = sipv[0];
                #pragma unroll
                for (int c = 0; c < NB; c++) { t[c] *= ip; sp[0][c] = t[c]; }
            }
            #pragma unroll
            for (int p = 0; p < NB; p++) {
                __syncthreads();
                const int gp = c0g + p;
                if (r != gp) {
                    const float f = m[p];
                    #pragma unroll
                    for (int c = 0; c < NB; c += 4) {
                        float4 s4 = *(const float4*)&sp[p & 1][c];
                        t[c + 0] -= f * s4.x; t[c + 1] -= f * s4.y;
                        t[c + 2] -= f * s4.z; t[c + 3] -= f * s4.w;
                    }
                    if (p + 1 < NB && r == gp + 1) {
                        const float ip2 = sipv[p + 1];
                        #pragma unroll
                        for (int c = 0; c < NB; c++) { t[c] *= ip2; sp[(p + 1) & 1][c] = t[c]; }
                    }
                }
            }
        }
    }

    #pragma unroll
    for (int c = 0; c < NB; c += 4)
        *(float4*)&g_M[l][r * U + j0 + c] = *(float4*)&t[c];
}

// =====================================================================
// 2) full 256-K GEMM body (proven round-5 code)
// =====================================================================
__device__ __forceinline__ void gemm64_body(const float* __restrict__ A,
                                            const float* __restrict__ Bm,
                                            float* __restrict__ C, int mode,
                                            int bx, int by) {
    __shared__ __align__(16) float As[32][68];
    __shared__ __align__(16) float Bs[32][68];
    const int tid = threadIdx.x;
    const int i0 = by * 64, j0 = bx * 64;
    const int rf = (tid >> 4) * 4, cf = (tid & 15) * 4;
    float acc[4][4];
    #pragma unroll
    for (int r = 0; r < 4; r++)
        #pragma unroll
        for (int c = 0; c < 4; c++) acc[r][c] = 0.0f;

    for (int k0 = 0; k0 < U; k0 += 32) {
        #pragma unroll
        for (int m = 0; m < 2; m++) {
            int s = tid + m * 256;
            int ii = s >> 3, kc = (s & 7) * 4;
            float4 a = *(const float4*)&A[(i0 + ii) * U + k0 + kc];
            As[kc + 0][ii] = a.x; As[kc + 1][ii] = a.y;
            As[kc + 2][ii] = a.z; As[kc + 3][ii] = a.w;
            int kk = s >> 4, jc = (s & 15) * 4;
            *(float4*)&Bs[kk][jc] = *(const float4*)&Bm[(k0 + kk) * U + j0 + jc];
        }
        __syncthreads();
        #pragma unroll
        for (int kk = 0; kk < 32; kk++) {
            float4 a4 = *(const float4*)&As[kk][rf];
            float4 b4 = *(const float4*)&Bs[kk][cf];
            float av[4] = {a4.x, a4.y, a4.z, a4.w};
            float bv[4] = {b4.x, b4.y, b4.z, b4.w};
            #pragma unroll
            for (int r = 0; r < 4; r++)
                #pragma unroll
                for (int c = 0; c < 4; c++) acc[r][c] += av[r] * bv[c];
        }
        __syncthreads();
    }
    #pragma unroll
    for (int r = 0; r < 4; r++) {
        int i = i0 + rf + r;
        #pragma unroll
        for (int c = 0; c < 4; c++) {
            int j = j0 + cf + c;
            float v = acc[r][c];
            if (mode) v = ((i == j) ? 2.0f : 0.0f) - v;
            C[i * U + j] = v;
        }
    }
}

__global__ __launch_bounds__(256) void newton64_kernel(const float* __restrict__ A,
                                                       const float* __restrict__ Bm,
                                                       float* __restrict__ C, int mode) {
    const int l = blockIdx.z;
    gemm64_body(A + (size_t)l * SZ, Bm + (size_t)l * SZ, C + (size_t)l * SZ,
                mode, blockIdx.x, blockIdx.y);
}

// generic z-strided product for the chain tree (strides in SZ units)
__global__ __launch_bounds__(256) void gemmz_kernel(const float* __restrict__ A, int sA,
                                                    const float* __restrict__ Bm, int sB,
                                                    float* __restrict__ C, int sC) {
    const int z = blockIdx.z;
    gemm64_body(A + (size_t)z * sA * SZ, Bm + (size_t)z * sB * SZ,
                C + (size_t)z * sC * SZ, 0, blockIdx.x, blockIdx.y);
}

// =====================================================================
// 3) Newton M2 = M*R with fused transposed-negated store to g_MTn.
// =====================================================================
__global__ __launch_bounds__(256) void newtonM2T_kernel() {
    const int l = blockIdx.z;
    const float* A  = g_M[l];
    const float* Bm = g_R[l];
    __shared__ __align__(16) float As[32][68];
    __shared__ __align__(16) float Bs[32][68];
    const int tid = threadIdx.x;
    const int i0 = blockIdx.y * 64, j0 = blockIdx.x * 64;
    const int rf = (tid >> 4) * 4, cf = (tid & 15) * 4;
    float acc[4][4];
    #pragma unroll
    for (int r = 0; r < 4; r++)
        #pragma unroll
        for (int c = 0; c < 4; c++) acc[r][c] = 0.0f;

    for (int k0 = 0; k0 < U; k0 += 32) {
        #pragma unroll
        for (int m = 0; m < 2; m++) {
            int s = tid + m * 256;
            int ii = s >> 3, kc = (s & 7) * 4;
            float4 a = *(const float4*)&A[(i0 + ii) * U + k0 + kc];
            As[kc + 0][ii] = a.x; As[kc + 1][ii] = a.y;
            As[kc + 2][ii] = a.z; As[kc + 3][ii] = a.w;
            int kk = s >> 4, jc = (s & 15) * 4;
            *(float4*)&Bs[kk][jc] = *(const float4*)&Bm[(k0 + kk) * U + j0 + jc];
        }
        __syncthreads();
        #pragma unroll
        for (int kk = 0; kk < 32; kk++) {
            float4 a4 = *(const float4*)&As[kk][rf];
            float4 b4 = *(const float4*)&Bs[kk][cf];
            float av[4] = {a4.x, a4.y, a4.z, a4.w};
            float bv[4] = {b4.x, b4.y, b4.z, b4.w};
            #pragma unroll
            for (int r = 0; r < 4; r++)
                #pragma unroll
                for (int c = 0; c < 4; c++) acc[r][c] += av[r] * bv[c];
        }
        __syncthreads();
    }
    #pragma unroll
    for (int r = 0; r < 4; r++) {
        const int i = i0 + rf + r;
        *(float4*)&g_M2[l][i * U + j0 + cf] =
            make_float4(acc[r][0], acc[r][1], acc[r][2], acc[r][3]);
    }
    #pragma unroll
    for (int c = 0; c < 4; c++) {
        const int j = j0 + cf + c;
        *(float4*)&g_MTn[l][j * U + i0 + rf] =
            make_float4(-acc[0][c], -acc[1][c], -acc[2][c], -acc[3][c]);
    }
}

// =====================================================================
// 4) constant chain, ALL 6 layers in one launch (512 threads).
//    half 0: c0' = MTn_l * c1 ; half 1: c1' = M2_l * (c0 + q_l)
// =====================================================================
__global__ __launch_bounds__(512) void constall_kernel(const float* __restrict__ q) {
    __shared__ float c0s[U], c1s[U], rq[U];
    const int tid = threadIdx.x;
    const int half = tid >> 8, n = tid & 255;
    if (tid < U) { c0s[tid] = 0.0f; c1s[tid] = 0.0f; }
    for (int l = 0; l < NL; l++) {
        __syncthreads();
        if (tid < U) rq[tid] = c0s[tid] + q[l * U + tid];
        __syncthreads();
        const float* A = half ? &g_M2[l][0] : &g_MTn[l][0];
        const float* v = half ? rq : c1s;
        float acc = 0.0f;
        for (int m = 0; m < U; m += 4) {
            float4 a4 = *(const float4*)&A[n * U + m];
            acc += a4.x * v[m];
            acc += a4.y * v[m + 1];
            acc += a4.z * v[m + 2];
            acc += a4.w * v[m + 3];
        }
        __syncthreads();
        if (half) c1s[n] = acc; else c0s[n] = acc;
    }
    __syncthreads();
    if (tid < U) g_c[tid] = c0s[tid];
}

// =====================================================================
// 5) foldG / foldF / final (proven round-5 code)
// =====================================================================
__global__ __launch_bounds__(256) void foldG_kernel(const float* __restrict__ Wout,
                                                    const float* __restrict__ K,
                                                    const float* __restrict__ c0,
                                                    const float* __restrict__ bin,
                                                    const float* __restrict__ bout) {
    __shared__ float Ws[U * DOUT];
    __shared__ float Gs[DOUT][U];
    const int m = threadIdx.x;
    for (int e = m; e < U * DOUT; e += 256) Ws[e] = Wout[e];
    __syncthreads();
    float acc[DOUT];
    #pragma unroll
    for (int d = 0; d < DOUT; d++) acc[d] = 0.0f;
    for (int n = 0; n < U; n++) {
        const float xv = K[n * U + m];
        #pragma unroll
        for (int d = 0; d < DOUT; d++) acc[d] += Ws[n * DOUT + d] * xv;
    }
    #pragma unroll
    for (int d = 0; d < DOUT; d++) { g_G[d * U + m] = acc[d]; Gs[d][m] = acc[d]; }
    __syncthreads();
    if (m < DOUT) {
        float f = bout[m];
        for (int e = 0; e < U; e++) f += Gs[m][e] * bin[e];
        for (int n = 0; n < U; n++) f += Ws[n * DOUT + m] * c0[n];
        g_f[m] = f;
    }
}

__global__ __launch_bounds__(256) void foldF_kernel(const float* __restrict__ Win) {
    __shared__ float Gs[DOUT * U];
    const int tid = threadIdx.x;
    for (int e = tid; e < DOUT * U; e += 256) Gs[e] = g_G[e];
    __syncthreads();
    const int k = blockIdx.x * 256 + tid;
    if (k >= DIN) return;
    float acc[DOUT];
    #pragma unroll
    for (int d = 0; d < DOUT; d++) acc[d] = 0.0f;
    for (int m = 0; m < U; m++) {
        const float w = Win[(size_t)k * U + m];
        #pragma unroll
        for (int d = 0; d < DOUT; d++) acc[d] += Gs[d * U + m] * w;
    }
    #pragma unroll
    for (int d = 0; d < DOUT; d++) g_F[k * DOUT + d] = acc[d];
}

__global__ __launch_bounds__(128) void final_kernel(const float* __restrict__ x,
                                                    float* __restrict__ out) {
    __shared__ float Fs[DIN * DOUT];
    __shared__ float fsv[16];
    __shared__ __align__(16) float xs[4][16 * 33];
    const int tid = threadIdx.x;
    for (int e = tid; e < DIN * DOUT; e += 128) Fs[e] = g_F[e];
    if (tid < DOUT) fsv[tid] = g_f[tid];
    __syncthreads();

    const int w = tid >> 5, lane = tid & 31;
    const int row0 = blockIdx.x * 128 + w * 32;
    float* xw = xs[w];
    float acc[DOUT];
    #pragma unroll
    for (int d = 0; d < DOUT; d++) acc[d] = fsv[d];

    for (int k0 = 0; k0 < DIN; k0 += 16) {
        #pragma unroll
        for (int i = 0; i < 4; i++) {
            const int s = lane + 32 * i;
            const int r = s >> 2, kc = (s & 3) * 4;
            float4 v = *(const float4*)&x[(size_t)(row0 + r) * DIN + k0 + kc];
            xw[(kc + 0) * 33 + r] = v.x;
            xw[(kc + 1) * 33 + r] = v.y;
            xw[(kc + 2) * 33 + r] = v.z;
            xw[(kc + 3) * 33 + r] = v.w;
        }
        __syncwarp();
        #pragma unroll
        for (int kk = 0; kk < 16; kk++) {
            const float xv = xw[kk * 33 + lane];
            const float* Fp = &Fs[(k0 + kk) * DOUT];
            #pragma unroll
            for (int d = 0; d < DOUT; d++) acc[d] += xv * Fp[d];
        }
        __syncwarp();
    }
    const size_t j = (size_t)row0 + lane;
    #pragma unroll
    for (int d = 0; d < DOUT; d++) out[j * DOUT + d] = acc[d];
}

// =====================================================================
// launch  (11 launches total)
// =====================================================================
extern "C" void kernel_launch(void* const* d_in, const int* in_sizes, int n_in,
                              void* d_out, int out_size) {
    const float* x    = (const float*)d_in[0];
    const float* Win  = (const float*)d_in[1];
    const float* bin  = (const float*)d_in[2];
    const float* B0   = (const float*)d_in[3];
    const float* q    = (const float*)d_in[4];
    const float* Wout = (const float*)d_in[5];
    const float* bout = (const float*)d_in[6];
    float* out = (float*)d_out;

    float *pM, *pR, *pMTn, *pc;
    cudaGetSymbolAddress((void**)&pM,   g_M);
    cudaGetSymbolAddress((void**)&pR,   g_R);
    cudaGetSymbolAddress((void**)&pMTn, g_MTn);
    cudaGetSymbolAddress((void**)&pc,   g_c);

    // --- persistent one-launch GENP inversion ---
    initflags_kernel<<<1, 64>>>();
    invert_kernel<<<dim3(NSTEP, NL), 256>>>(B0);

    // --- 1 Newton-Schulz step; M2 + (-M2^T) fused ---
    dim3 ng(4, 4, NL);
    newton64_kernel<<<ng, 256>>>(B0, pM, pR, 1);    // R = 2I - B0*M
    newtonM2T_kernel<<<ng, 256>>>();                // M2 = M*R, MTn = -M2^T

    // --- chain tree: K = T2*(T1*T0), T_z = MTn[2z+1]*M2[2z]  (g_M reused) ---
    float* pM2s;
    cudaGetSymbolAddress((void**)&pM2s, g_M2);
    gemmz_kernel<<<dim3(4, 4, 3), 256>>>(pMTn + SZ, 2, pM2s, 2, pM, 1);
    gemmz_kernel<<<dim3(4, 4, 1), 256>>>(pM + SZ, 0, pM, 0, pM + 3 * (size_t)SZ, 0);
    gemmz_kernel<<<dim3(4, 4, 1), 256>>>(pM + 2 * (size_t)SZ, 0, pM + 3 * (size_t)SZ, 0,
                                         pM + 4 * (size_t)SZ, 0);

    // --- constant chain in one launch ---
    constall_kernel<<<1, 512>>>(q);

    // --- fold into F (10x784) and f (10) ---
    foldG_kernel<<<1, 256>>>(Wout, pM + 4 * (size_t)SZ, pc, bin, bout);
    foldF_kernel<<<4, 256>>>(Win);

    // --- single memory-bound pass over x ---
    final_kernel<<<BATCH / 128, 128>>>(x, out);
}

// round 13
// speedup vs baseline: 17.8617x; 1.0847x over previous
#include <cuda_runtime.h>
#include <math.h>
#include <stdint.h>

#define U     256
#define SZ    65536          // U*U
#define BATCH 32768
#define NL    6
#define DIN   784
#define DOUT  10
#define NB    32             // panel width
#define NSTEP (U / NB)       // 8 block steps
#define NCTA  96             // mega-kernel grid (<=148 SMs -> co-resident)

// ===================== device-global scratch (no runtime allocs) =====================
__device__ float g_M   [NL][SZ];          // GENP inverse; later reused as tree bufs
__device__ float g_M2  [NL][SZ];          // Newton-refined inverse
__device__ float g_R   [NL][SZ];          // Newton residual
__device__ float g_MTn [NL][SZ];          // -(M2)^T
__device__ float g_Mul8[NSTEP][NL][NB * U]; // multipliers, per-step buffers, [p][r]
__device__ float g_ipiv[NL][U];           // 1/pivot per global step
__device__ unsigned int g_flagw[NL][NSTEP];
__device__ float g_c   [U];               // final constant c0
__device__ float g_G   [DOUT * U];
__device__ float g_F   [DIN * DOUT];
__device__ float g_f   [16];
__device__ unsigned int g_barcnt = 0;     // grid barrier state
__device__ unsigned int g_bargen = 0;

// =====================================================================
// device-wide barrier (sense via generation counter; snapshot BEFORE arrive)
// =====================================================================
__device__ __forceinline__ void grid_sync() {
    __syncthreads();
    if (threadIdx.x == 0) {
        __threadfence();
        const unsigned int gen = atomicAdd(&g_bargen, 0u);
        if (atomicAdd(&g_barcnt, 1u) == NCTA - 1) {
            g_barcnt = 0;
            __threadfence();
            atomicAdd(&g_bargen, 1u);
        } else {
            while (atomicAdd(&g_bargen, 0u) == gen) { }
        }
    }
    __syncthreads();
}

// =====================================================================
// inversion body (proven round-12 arithmetic), CTA = (tile jt, layer l)
// =====================================================================
__device__ void invert_body(const float* __restrict__ B0, int l, int jt,
                            float (*sp)[NB], float* sipv) {
    const int r = threadIdx.x;
    const float* A = B0 + (size_t)l * SZ;
    const int j0 = jt * NB;

    float t[NB];
    #pragma unroll
    for (int c = 0; c < NB; c += 4)
        *(float4*)&t[c] = *(const float4*)&A[r * U + j0 + c];

    #pragma unroll 1
    for (int kb = 0; kb < NSTEP; kb++) {
        float* Mul = &g_Mul8[kb][l][0];
        const int c0g = kb * NB;
        if (jt == kb) {
            if (r == c0g) {
                Mul[0 * U + r] = t[0];
                const float ip = 1.0f / t[0];
                g_ipiv[l][c0g] = ip;
                #pragma unroll
                for (int c = 0; c < NB; c++) t[c] = (c == 0) ? ip : t[c] * ip;
                #pragma unroll
                for (int c = 0; c < NB; c++) sp[0][c] = t[c];
            }
            #pragma unroll
            for (int p = 0; p < NB; p++) {
                __syncthreads();
                const int gp = c0g + p;
                if (r != gp) {
                    const float f = t[p];
                    Mul[p * U + r] = f;
                    const float ip = sp[p & 1][p];
                    #pragma unroll
                    for (int c = 0; c < NB; c += 4) {
                        float4 s4 = *(const float4*)&sp[p & 1][c];
                        t[c + 0] -= f * s4.x; t[c + 1] -= f * s4.y;
                        t[c + 2] -= f * s4.z; t[c + 3] -= f * s4.w;
                    }
                    t[p] = -f * ip;
                    if (p + 1 < NB && r == gp + 1) {
                        Mul[(p + 1) * U + r] = t[p + 1];
                        const float ip2 = 1.0f / t[p + 1];
                        g_ipiv[l][gp + 1] = ip2;
                        #pragma unroll
                        for (int c = 0; c < NB; c++)
                            t[c] = (c == p + 1) ? ip2 : t[c] * ip2;
                        #pragma unroll
                        for (int c = 0; c < NB; c++) sp[(p + 1) & 1][c] = t[c];
                    }
                }
            }
            __threadfence();
            __syncthreads();
            if (r == 0) atomicExch(&g_flagw[l][kb], 1u);
        } else {
            if (r == 0) {
                while (atomicAdd(&g_flagw[l][kb], 0u) == 0u) { }
            }
            __syncthreads();
            float m[NB];
            #pragma unroll
            for (int p = 0; p < NB; p++) m[p] = Mul[p * U + r];
            if (r < NB) sipv[r] = g_ipiv[l][c0g + r];
            __syncthreads();
            if (r == c0g) {
                const float ip = sipv[0];
                #pragma unroll
                for (int c = 0; c < NB; c++) { t[c] *= ip; sp[0][c] = t[c]; }
            }
            #pragma unroll
            for (int p = 0; p < NB; p++) {
                __syncthreads();
                const int gp = c0g + p;
                if (r != gp) {
                    const float f = m[p];
                    #pragma unroll
                    for (int c = 0; c < NB; c += 4) {
                        float4 s4 = *(const float4*)&sp[p & 1][c];
                        t[c + 0] -= f * s4.x; t[c + 1] -= f * s4.y;
                        t[c + 2] -= f * s4.z; t[c + 3] -= f * s4.w;
                    }
                    if (p + 1 < NB && r == gp + 1) {
                        const float ip2 = sipv[p + 1];
                        #pragma unroll
                        for (int c = 0; c < NB; c++) { t[c] *= ip2; sp[(p + 1) & 1][c] = t[c]; }
                    }
                }
            }
        }
    }

    #pragma unroll
    for (int c = 0; c < NB; c += 4)
        *(float4*)&g_M[l][r * U + j0 + c] = *(float4*)&t[c];
}

// =====================================================================
// 64x64x256 GEMM tile body on a caller-provided smem buffer
//   mode 0: C = A*B       mode 1: C = 2I - A*B
//   mode 2: C = A*B, plus transposed-negated store to T (newton M2+MTn)
// =====================================================================
__device__ void gemm_tile(float* shbuf,
                          const float* __restrict__ A, const float* __restrict__ Bm,
                          float* __restrict__ C, float* __restrict__ T,
                          int mode, int bx, int by) {
    float (*As)[68] = (float(*)[68])shbuf;
    float (*Bs)[68] = (float(*)[68])(shbuf + 32 * 68);
    const int tid = threadIdx.x;
    const int i0 = by * 64, j0 = bx * 64;
    const int rf = (tid >> 4) * 4, cf = (tid & 15) * 4;
    float acc[4][4];
    #pragma unroll
    for (int r = 0; r < 4; r++)
        #pragma unroll
        for (int c = 0; c < 4; c++) acc[r][c] = 0.0f;

    for (int k0 = 0; k0 < U; k0 += 32) {
        #pragma unroll
        for (int m = 0; m < 2; m++) {
            int s = tid + m * 256;
            int ii = s >> 3, kc = (s & 7) * 4;
            float4 a = *(const float4*)&A[(i0 + ii) * U + k0 + kc];
            As[kc + 0][ii] = a.x; As[kc + 1][ii] = a.y;
            As[kc + 2][ii] = a.z; As[kc + 3][ii] = a.w;
            int kk = s >> 4, jc = (s & 15) * 4;
            *(float4*)&Bs[kk][jc] = *(const float4*)&Bm[(k0 + kk) * U + j0 + jc];
        }
        __syncthreads();
        #pragma unroll
        for (int kk = 0; kk < 32; kk++) {
            float4 a4 = *(const float4*)&As[kk][rf];
            float4 b4 = *(const float4*)&Bs[kk][cf];
            float av[4] = {a4.x, a4.y, a4.z, a4.w};
            float bv[4] = {b4.x, b4.y, b4.z, b4.w};
            #pragma unroll
            for (int r = 0; r < 4; r++)
                #pragma unroll
                for (int c = 0; c < 4; c++) acc[r][c] += av[r] * bv[c];
        }
        __syncthreads();
    }
    if (mode == 2) {
        #pragma unroll
        for (int r = 0; r < 4; r++) {
            const int i = i0 + rf + r;
            *(float4*)&C[i * U + j0 + cf] =
                make_float4(acc[r][0], acc[r][1], acc[r][2], acc[r][3]);
        }
        #pragma unroll
        for (int c = 0; c < 4; c++) {
            const int j = j0 + cf + c;
            *(float4*)&T[j * U + i0 + rf] =
                make_float4(-acc[0][c], -acc[1][c], -acc[2][c], -acc[3][c]);
        }
    } else {
        #pragma unroll
        for (int r = 0; r < 4; r++) {
            int i = i0 + rf + r;
            #pragma unroll
            for (int c = 0; c < 4; c++) {
                int j = j0 + cf + c;
                float v = acc[r][c];
                if (mode == 1) v = ((i == j) ? 2.0f : 0.0f) - v;
                C[i * U + j] = v;
            }
        }
    }
}

// =====================================================================
// constant-chain layers [l0,l1): c0' = MTn_l*c1 ; c1' = M2_l*(c0+q_l)
// (state persists in CTA95's smem across phases)
// =====================================================================
__device__ void const_layers(int l0, int l1, const float* __restrict__ q,
                             float* c0s, float* c1s, float* rq) {
    const int n = threadIdx.x;
    for (int l = l0; l < l1; l++) {
        __syncthreads();
        rq[n] = c0s[n] + q[l * U + n];
        __syncthreads();
        const float* A0 = &g_MTn[l][0];
        const float* A1 = &g_M2[l][0];
        float acc0 = 0.0f, acc1 = 0.0f;
        for (int m = 0; m < U; m += 4) {
            float4 a4 = *(const float4*)&A0[n * U + m];
            acc0 += a4.x * c1s[m];     acc0 += a4.y * c1s[m + 1];
            acc0 += a4.z * c1s[m + 2]; acc0 += a4.w * c1s[m + 3];
            float4 b4 = *(const float4*)&A1[n * U + m];
            acc1 += b4.x * rq[m];      acc1 += b4.y * rq[m + 1];
            acc1 += b4.z * rq[m + 2];  acc1 += b4.w * rq[m + 3];
        }
        __syncthreads();
        c0s[n] = acc0; c1s[n] = acc1;
    }
}

// =====================================================================
// foldG (proven, single CTA): G = Wout^T*K; f = G*bin + Wout^T*c0 + bout
// shbuf layout: Ws = shbuf[0..2560), Gs = shbuf[2560..5120)
// =====================================================================
__device__ void foldG_body(float* shbuf, const float* __restrict__ Wout,
                           const float* __restrict__ K, const float* __restrict__ c0,
                           const float* __restrict__ bin, const float* __restrict__ bout) {
    float* Ws = shbuf;
    float* Gs = shbuf + U * DOUT;
    const int m = threadIdx.x;
    for (int e = m; e < U * DOUT; e += 256) Ws[e] = Wout[e];
    __syncthreads();
    float acc[DOUT];
    #pragma unroll
    for (int d = 0; d < DOUT; d++) acc[d] = 0.0f;
    for (int n = 0; n < U; n++) {
        const float xv = K[n * U + m];
        #pragma unroll
        for (int d = 0; d < DOUT; d++) acc[d] += Ws[n * DOUT + d] * xv;
    }
    #pragma unroll
    for (int d = 0; d < DOUT; d++) { g_G[d * U + m] = acc[d]; Gs[d * U + m] = acc[d]; }
    __syncthreads();
    if (m < DOUT) {
        float f = bout[m];
        for (int e = 0; e < U; e++) f += Gs[m * U + e] * bin[e];
        for (int n = 0; n < U; n++) f += Ws[n * DOUT + m] * c0[n];
        g_f[m] = f;
    }
}

// =====================================================================
// foldF (proven): F[k][d] = sum_m G[d][m] * Win[k][m];  shbuf: Gs[2560]
// =====================================================================
__device__ void foldF_body(float* shbuf, const float* __restrict__ Win, int blk) {
    float* Gs = shbuf;
    const int tid = threadIdx.x;
    for (int e = tid; e < DOUT * U; e += 256) Gs[e] = g_G[e];
    __syncthreads();
    const int k = blk * 256 + tid;
    if (k >= DIN) return;
    float acc[DOUT];
    #pragma unroll
    for (int d = 0; d < DOUT; d++) acc[d] = 0.0f;
    for (int m = 0; m < U; m++) {
        const float w = Win[(size_t)k * U + m];
        #pragma unroll
        for (int d = 0; d < DOUT; d++) acc[d] += Gs[d * U + m] * w;
    }
    #pragma unroll
    for (int d = 0; d < DOUT; d++) g_F[k * DOUT + d] = acc[d];
}

// =====================================================================
// THE mega kernel: all setup phases in one launch, grid-barrier synced
// =====================================================================
__global__ __launch_bounds__(256) void mega_kernel(const float* __restrict__ B0,
                                                   const float* __restrict__ q,
                                                   const float* __restrict__ Wout,
                                                   const float* __restrict__ bin,
                                                   const float* __restrict__ bout,
                                                   const float* __restrict__ Win) {
    __shared__ __align__(16) float shbuf[5376];   // gemm tiles / fold buffers
    __shared__ __align__(16) float sp[2][NB];
    __shared__ float sipv[NB];
    __shared__ float c0s[U], c1s[U], rq[U];
    const int cta = blockIdx.x;
    const int tid = threadIdx.x;

    // P0: reset inversion flags
    if (cta == 0 && tid < NL * NSTEP) ((unsigned int*)g_flagw)[tid] = 0u;
    grid_sync();

    // P1: flag-synced GENP inversion (48 CTAs)
    if (cta < 48) invert_body(B0, cta >> 3, cta & 7, sp, sipv);
    grid_sync();

    // P2: R = 2I - B0*M   (96 tiles)
    {
        const int l = cta >> 4, t = cta & 15;
        gemm_tile(shbuf, B0 + (size_t)l * SZ, g_M[l], g_R[l], nullptr, 1, t & 3, t >> 2);
    }
    grid_sync();

    // P3: M2 = M*R with fused MTn = -M2^T   (96 tiles)
    {
        const int l = cta >> 4, t = cta & 15;
        gemm_tile(shbuf, g_M[l], g_R[l], g_M2[l], g_MTn[l], 2, t & 3, t >> 2);
    }
    grid_sync();

    // P4: chain level 1: T_z = MTn[2z+1]*M2[2z] -> g_M[z]  (48 tiles)
    //     CTA 95: constant chain layers 0-1
    if (cta < 48) {
        const int z = cta >> 4, t = cta & 15;
        gemm_tile(shbuf, g_MTn[2 * z + 1], g_M2[2 * z], g_M[z], nullptr, 0, t & 3, t >> 2);
    } else if (cta == 95) {
        c0s[tid] = 0.0f; c1s[tid] = 0.0f;
        const_layers(0, 2, q, c0s, c1s, rq);
    }
    grid_sync();

    // P5: TT = T1*T0 -> g_M[3]  (16 tiles);  CTA 95: const layers 2-3
    if (cta < 16) gemm_tile(shbuf, g_M[1], g_M[0], g_M[3], nullptr, 0, cta & 3, cta >> 2);
    else if (cta == 95) const_layers(2, 4, q, c0s, c1s, rq);
    grid_sync();

    // P6: K = T2*TT -> g_M[4]  (16 tiles);  CTA 95: const layers 4-5 + publish c0
    if (cta < 16) gemm_tile(shbuf, g_M[2], g_M[3], g_M[4], nullptr, 0, cta & 3, cta >> 2);
    else if (cta == 95) {
        const_layers(4, 6, q, c0s, c1s, rq);
        g_c[tid] = c0s[tid];
    }
    grid_sync();

    // P7: foldG (CTA 0)
    if (cta == 0) foldG_body(shbuf, Wout, g_M[4], g_c, bin, bout);
    grid_sync();

    // P8: foldF (CTAs 0-3)
    if (cta < 4) foldF_body(shbuf, Win, cta);
}

// =====================================================================
// final: out[j][:] = F * x[j][:] + f  (proven round-5 code)
// =====================================================================
__global__ __launch_bounds__(128) void final_kernel(const float* __restrict__ x,
                                                    float* __restrict__ out) {
    __shared__ float Fs[DIN * DOUT];
    __shared__ float fsv[16];
    __shared__ __align__(16) float xs[4][16 * 33];
    const int tid = threadIdx.x;
    for (int e = tid; e < DIN * DOUT; e += 128) Fs[e] = g_F[e];
    if (tid < DOUT) fsv[tid] = g_f[tid];
    __syncthreads();

    const int w = tid >> 5, lane = tid & 31;
    const int row0 = blockIdx.x * 128 + w * 32;
    float* xw = xs[w];
    float acc[DOUT];
    #pragma unroll
    for (int d = 0; d < DOUT; d++) acc[d] = fsv[d];

    for (int k0 = 0; k0 < DIN; k0 += 16) {
        #pragma unroll
        for (int i = 0; i < 4; i++) {
            const int s = lane + 32 * i;
            const int r = s >> 2, kc = (s & 3) * 4;
            float4 v = *(const float4*)&x[(size_t)(row0 + r) * DIN + k0 + kc];
            xw[(kc + 0) * 33 + r] = v.x;
            xw[(kc + 1) * 33 + r] = v.y;
            xw[(kc + 2) * 33 + r] = v.z;
            xw[(kc + 3) * 33 + r] = v.w;
        }
        __syncwarp();
        #pragma unroll
        for (int kk = 0; kk < 16; kk++) {
            const float xv = xw[kk * 33 + lane];
            const float* Fp = &Fs[(k0 + kk) * DOUT];
            #pragma unroll
            for (int d = 0; d < DOUT; d++) acc[d] += xv * Fp[d];
        }
        __syncwarp();
    }
    const size_t j = (size_t)row0 + lane;
    #pragma unroll
    for (int d = 0; d < DOUT; d++) out[j * DOUT + d] = acc[d];
}

// =====================================================================
// launch  (2 launches total)
// =====================================================================
extern "C" void kernel_launch(void* const* d_in, const int* in_sizes, int n_in,
                              void* d_out, int out_size) {
    const float* x    = (const float*)d_in[0];
    const float* Win  = (const float*)d_in[1];
    const float* bin  = (const float*)d_in[2];
    const float* B0   = (const float*)d_in[3];
    const float* q    = (const float*)d_in[4];
    const float* Wout = (const float*)d_in[5];
    const float* bout = (const float*)d_in[6];
    float* out = (float*)d_out;

    mega_kernel<<<NCTA, 256>>>(B0, q, Wout, bin, bout, Win);
    final_kernel<<<BATCH / 128, 128>>>(x, out);
}